// round 7
// baseline (speedup 1.0000x reference)
#include <cuda_runtime.h>
#include <cuda_bf16.h>
#include <cstdint>

// ============================================================================
//   x : (3, 8192) fp32   W1 : (8192, 64)   W2 : (64, 64)   W3 : (64, 1)
//   out = mean(per_row MLP(corr)) - regu2*sum(x2) - regu*sum(exp(x2/(2 rl^2)))
//   corr[i,j] = sum_c x[c,(i+j)%N] * x[c,i]
//
//   R7: corr-build uses packed f32x2 FMA (FFMA2) fused into bf16x2 cvt;
//   band staging 3 LDG/elem (odd copy = even shifted); w1prep 512x128.
// ============================================================================
#define NTOK 8192
#define KQUART 2048
#define BANDLEN 2336                     // 2048 + 256 + slack, mult of 32
#define ODD_OFF (3 * BANDLEN + 16)       // +16 floats: disjoint banks vs even

__device__ double g_acc[3];                               // sum_x2, sum_exp, sum_per_row
__device__ unsigned int g_done;                           // mlp completion counter
__device__ __align__(16) float g_partial[4 * NTOK * 64];  // [kq][row][f], 8MB
__device__ __align__(16) uint32_t g_w1p[512 * 32 * 16];   // [ks][lane][nt*2+r] bf16x2

__device__ __forceinline__ uint32_t pack_bf16x2(float lo, float hi) {
    uint32_t r;
    asm("cvt.rn.bf16x2.f32 %0, %1, %2;" : "=r"(r) : "f"(hi), "f"(lo));
    return r;
}
__device__ __forceinline__ uint64_t pack2f(float v) {
    uint64_t r;
    asm("mov.b64 %0, {%1, %1};" : "=l"(r) : "f"(v));
    return r;
}
// (x0,x1,x2 broadcast-packed) . (u,v,w packed pairs) -> bf16x2(lo,hi)
__device__ __forceinline__ uint32_t dot3cvt(uint64_t x0, uint64_t x1, uint64_t x2,
                                            uint64_t u, uint64_t v, uint64_t w) {
    uint32_t out;
    asm("{\n\t"
        ".reg .b64 t;\n\t"
        ".reg .b32 lo, hi;\n\t"
        "mul.rn.f32x2 t, %3, %6;\n\t"
        "fma.rn.f32x2 t, %2, %5, t;\n\t"
        "fma.rn.f32x2 t, %1, %4, t;\n\t"
        "mov.b64 {lo, hi}, t;\n\t"
        "cvt.rn.bf16x2.f32 %0, hi, lo;\n\t"
        "}"
        : "=r"(out)
        : "l"(x0), "l"(x1), "l"(x2), "l"(u), "l"(v), "l"(w));
    return out;
}
__device__ __forceinline__ float elu1(float v) { return v > 0.f ? v : expm1f(v); }

#define MMA_BF16(d0,d1,d2,d3,a0,a1,a2,a3,b0,b1) \
    asm volatile("mma.sync.aligned.m16n8k16.row.col.f32.bf16.bf16.f32 " \
                 "{%0,%1,%2,%3}, {%4,%5,%6,%7}, {%8,%9}, {%0,%1,%2,%3};" \
                 : "+f"(d0), "+f"(d1), "+f"(d2), "+f"(d3) \
                 : "r"(a0), "r"(a1), "r"(a2), "r"(a3), "r"(b0), "r"(b1))

// ---------------------------------------------------------------------------
// K1: W1 -> m16n8k16 B fragments. 512 blocks x 128 thr, 1 k-step per block.
// ---------------------------------------------------------------------------
__global__ __launch_bounds__(128) void w1prep_kernel(const float* __restrict__ W1) {
    __shared__ float w[1024];
    if (blockIdx.x == 0 && threadIdx.x == 0) {
        g_acc[0] = 0.0; g_acc[1] = 0.0; g_acc[2] = 0.0; g_done = 0u;
    }
    const int b = blockIdx.x, tid = threadIdx.x;
    const float4* src = (const float4*)(W1 + b * 1024);   // k-rows [16b,16b+16) x 64
    ((float4*)w)[tid]       = src[tid];
    ((float4*)w)[tid + 128] = src[tid + 128];
    __syncthreads();

    uint32_t o4[4];
    #pragma unroll
    for (int j = 0; j < 4; j++) {
        const int o = tid * 4 + j;                        // 0..511
        const int lane = o >> 4;
        const int q = o & 15;
        const int nt = q >> 1, r = q & 1;
        const int k = (lane & 3) * 2 + r * 8;
        const int n = nt * 8 + (lane >> 2);
        o4[j] = pack_bf16x2(w[k * 64 + n], w[(k + 1) * 64 + n]);
    }
    ((uint4*)g_w1p)[b * 128 + tid] = make_uint4(o4[0], o4[1], o4[2], o4[3]);
}

// ---------------------------------------------------------------------------
// K2: fused corr-build (f32x2) + mma.sync bf16 GEMM (preact = corr @ W1)
//   grid = 128: (i-tile of 256 rows) x (K-quarter of 2048)
// ---------------------------------------------------------------------------
__global__ __launch_bounds__(256, 1) void gemm_kernel(const float* __restrict__ x) {
    extern __shared__ float band[];                   // even[3][BANDLEN] | pad16 | odd[3][BANDLEN]
    const int tid = threadIdx.x, warp = tid >> 5, lane = tid & 31;
    const int g = lane >> 2, t = lane & 3;
    const int it = blockIdx.x >> 2, kq = blockIdx.x & 3;
    const int i0 = it * 256, jbase = kq * KQUART;

    // stage: even[o]=x[base+o]; odd[o-1]=even[o] (odd copy = shift by 1)
    for (int o = tid; o < BANDLEN; o += 256) {
        const int s0 = (i0 + jbase + o) & (NTOK - 1);
        const float v0 = x[s0], v1 = x[NTOK + s0], v2 = x[2 * NTOK + s0];
        band[o]               = v0;
        band[BANDLEN + o]     = v1;
        band[2 * BANDLEN + o] = v2;
        if (o > 0) {
            band[ODD_OFF + o - 1]               = v0;
            band[ODD_OFF + BANDLEN + o - 1]     = v1;
            band[ODD_OFF + 2 * BANDLEN + o - 1] = v2;
        }
    }
    if (tid == 0) {           // odd tail (unused in practice, written for safety)
        const int s = (i0 + jbase + BANDLEN) & (NTOK - 1);
        band[ODD_OFF + BANDLEN - 1]     = x[s];
        band[ODD_OFF + 2 * BANDLEN - 1] = x[NTOK + s];
        band[ODD_OFF + 3 * BANDLEN - 1] = x[2 * NTOK + s];
    }

    // per-thread row scalars, broadcast-packed for f32x2
    const int r0 = i0 + warp * 32 + g;
    const uint64_t xA0 = pack2f(x[r0]),      xA1 = pack2f(x[NTOK + r0]),      xA2 = pack2f(x[2 * NTOK + r0]);
    const uint64_t xB0 = pack2f(x[r0 + 8]),  xB1 = pack2f(x[NTOK + r0 + 8]),  xB2 = pack2f(x[2 * NTOK + r0 + 8]);
    const uint64_t xC0 = pack2f(x[r0 + 16]), xC1 = pack2f(x[NTOK + r0 + 16]), xC2 = pack2f(x[2 * NTOK + r0 + 16]);
    const uint64_t xD0 = pack2f(x[r0 + 24]), xD1 = pack2f(x[NTOK + r0 + 24]), xD2 = pack2f(x[2 * NTOK + r0 + 24]);
    __syncthreads();

    // parity-corrected aligned pair pointers (each uint64 = 2 adjacent floats)
    const int par = g & 1;
    const int ib = (warp * 32 + g + 2 * t - par) >> 1;    // uint64 index
    const uint64_t* sb = (const uint64_t*)(band + (par ? ODD_OFF : 0));
    const uint64_t* p0 = sb + ib;
    const uint64_t* p1 = sb + (BANDLEN >> 1) + ib;
    const uint64_t* p2 = sb + BANDLEN + ib;

    const uint4* bp = (const uint4*)g_w1p + (size_t)(kq * 128) * 128 + lane * 4;

    float acc[2][8][4];
    #pragma unroll
    for (int s = 0; s < 2; s++)
        #pragma unroll
        for (int nt = 0; nt < 8; nt++)
            #pragma unroll
            for (int k = 0; k < 4; k++) acc[s][nt][k] = 0.f;

    // carried pairs at step offsets +0,+8,+16 per channel
    uint64_t u0 = p0[0], u1 = p0[4], u2 = p0[8];
    uint64_t v0 = p1[0], v1 = p1[4], v2 = p1[8];
    uint64_t w0 = p2[0], w1 = p2[4], w2 = p2[8];

    #pragma unroll 2
    for (int ks = 0; ks < 128; ks++) {
        const int e = ks * 8;
        const uint64_t u3 = p0[e + 12], u4 = p0[e + 16];  // fresh +24, +32
        const uint64_t v3 = p1[e + 12], v4 = p1[e + 16];
        const uint64_t w3 = p2[e + 12], w4 = p2[e + 16];

        const uint32_t a0 = dot3cvt(xA0, xA1, xA2, u0, v0, w0);   // (g,    k=2t)
        const uint32_t a2 = dot3cvt(xA0, xA1, xA2, u1, v1, w1);   // (g,    k=2t+8)
        const uint32_t a1 = dot3cvt(xB0, xB1, xB2, u1, v1, w1);   // (g+8,  k=2t)
        const uint32_t a3 = dot3cvt(xB0, xB1, xB2, u2, v2, w2);   // (g+8,  k=2t+8)
        const uint32_t c0 = dot3cvt(xC0, xC1, xC2, u2, v2, w2);   // (g+16, k=2t)
        const uint32_t c2 = dot3cvt(xC0, xC1, xC2, u3, v3, w3);   // (g+16, k=2t+8)
        const uint32_t c1 = dot3cvt(xD0, xD1, xD2, u3, v3, w3);   // (g+24, k=2t)
        const uint32_t c3 = dot3cvt(xD0, xD1, xD2, u4, v4, w4);   // (g+24, k=2t+8)

        const uint4 B0 = bp[0], B1 = bp[1], B2 = bp[2], B3 = bp[3];
        bp += 128;

        MMA_BF16(acc[0][0][0], acc[0][0][1], acc[0][0][2], acc[0][0][3], a0, a1, a2, a3, B0.x, B0.y);
        MMA_BF16(acc[0][1][0], acc[0][1][1], acc[0][1][2], acc[0][1][3], a0, a1, a2, a3, B0.z, B0.w);
        MMA_BF16(acc[0][2][0], acc[0][2][1], acc[0][2][2], acc[0][2][3], a0, a1, a2, a3, B1.x, B1.y);
        MMA_BF16(acc[0][3][0], acc[0][3][1], acc[0][3][2], acc[0][3][3], a0, a1, a2, a3, B1.z, B1.w);
        MMA_BF16(acc[0][4][0], acc[0][4][1], acc[0][4][2], acc[0][4][3], a0, a1, a2, a3, B2.x, B2.y);
        MMA_BF16(acc[0][5][0], acc[0][5][1], acc[0][5][2], acc[0][5][3], a0, a1, a2, a3, B2.z, B2.w);
        MMA_BF16(acc[0][6][0], acc[0][6][1], acc[0][6][2], acc[0][6][3], a0, a1, a2, a3, B3.x, B3.y);
        MMA_BF16(acc[0][7][0], acc[0][7][1], acc[0][7][2], acc[0][7][3], a0, a1, a2, a3, B3.z, B3.w);

        MMA_BF16(acc[1][0][0], acc[1][0][1], acc[1][0][2], acc[1][0][3], c0, c1, c2, c3, B0.x, B0.y);
        MMA_BF16(acc[1][1][0], acc[1][1][1], acc[1][1][2], acc[1][1][3], c0, c1, c2, c3, B0.z, B0.w);
        MMA_BF16(acc[1][2][0], acc[1][2][1], acc[1][2][2], acc[1][2][3], c0, c1, c2, c3, B1.x, B1.y);
        MMA_BF16(acc[1][3][0], acc[1][3][1], acc[1][3][2], acc[1][3][3], c0, c1, c2, c3, B1.z, B1.w);
        MMA_BF16(acc[1][4][0], acc[1][4][1], acc[1][4][2], acc[1][4][3], c0, c1, c2, c3, B2.x, B2.y);
        MMA_BF16(acc[1][5][0], acc[1][5][1], acc[1][5][2], acc[1][5][3], c0, c1, c2, c3, B2.z, B2.w);
        MMA_BF16(acc[1][6][0], acc[1][6][1], acc[1][6][2], acc[1][6][3], c0, c1, c2, c3, B3.x, B3.y);
        MMA_BF16(acc[1][7][0], acc[1][7][1], acc[1][7][2], acc[1][7][3], c0, c1, c2, c3, B3.z, B3.w);

        u0 = u2; u1 = u3; u2 = u4;
        v0 = v2; v1 = v3; v2 = v4;
        w0 = w2; w1 = w3; w2 = w4;
    }

    // epilogue: [kq][row][f] layout; quad-contiguous 32B-sector float2 stores
    float* basep = g_partial + (size_t)kq * (NTOK * 64);
    #pragma unroll
    for (int s = 0; s < 2; s++) {
        const int rA = r0 + 16 * s, rB = rA + 8;
        #pragma unroll
        for (int nt = 0; nt < 8; nt++) {
            const int n = nt * 8 + 2 * t;
            *(float2*)(basep + (size_t)rA * 64 + n) = make_float2(acc[s][nt][0], acc[s][nt][1]);
            *(float2*)(basep + (size_t)rB * 64 + n) = make_float2(acc[s][nt][2], acc[s][nt][3]);
        }
    }
}

// ---------------------------------------------------------------------------
// K3: MLP epilogue + regularization + final combine.
//   grid = 256 CTAs x 256 thr. Block owns 32 rows; warp owns 4 rows fused.
// ---------------------------------------------------------------------------
__global__ __launch_bounds__(256) void mlp_kernel(const float* __restrict__ x,
                                                  const float* __restrict__ W2,
                                                  const float* __restrict__ W3,
                                                  const float* __restrict__ regu2,
                                                  const float* __restrict__ regu,
                                                  const float* __restrict__ rl_p,
                                                  float* __restrict__ out) {
    __shared__ float w2s[4096];
    __shared__ float w3s[64];
    __shared__ float z1s[32][64];
    __shared__ float wsum[8];
    __shared__ float rsum[2];
    const int tid = threadIdx.x, warp = tid >> 5, lane = tid & 31;

    if (warp == 0) {
        const int tok = blockIdx.x * 32 + lane;
        const float a = x[tok], b = x[NTOK + tok], c = x[2 * NTOK + tok];
        float x2 = fmaf(a, a, fmaf(b, b, c * c));
        const float rl = rl_p[0];
        float e = expf(x2 / (2.f * rl * rl));
        #pragma unroll
        for (int o = 16; o > 0; o >>= 1) {
            x2 += __shfl_down_sync(0xFFFFFFFFu, x2, o);
            e  += __shfl_down_sync(0xFFFFFFFFu, e, o);
        }
        if (lane == 0) { rsum[0] = x2; rsum[1] = e; }
    }

    for (int tv = tid; tv < 4096; tv += 256) w2s[tv] = W2[tv];
    if (tid < 64) w3s[tid] = W3[tid];

    const int rbase = blockIdx.x * 32 + warp * 4;
    float2 pq[4][4];
    #pragma unroll
    for (int rr = 0; rr < 4; rr++)
        #pragma unroll
        for (int q = 0; q < 4; q++)
            pq[rr][q] = ((const float2*)(g_partial + ((size_t)q * NTOK + rbase + rr) * 64))[lane];

    #pragma unroll
    for (int rr = 0; rr < 4; rr++) {
        const float px = pq[rr][0].x + pq[rr][1].x + pq[rr][2].x + pq[rr][3].x;
        const float py = pq[rr][0].y + pq[rr][1].y + pq[rr][2].y + pq[rr][3].y;
        z1s[warp * 4 + rr][2 * lane]     = elu1(px);
        z1s[warp * 4 + rr][2 * lane + 1] = elu1(py);
    }
    __syncthreads();

    float2 a0 = make_float2(0.f, 0.f), a1 = a0, a2 = a0, a3 = a0;
    const float2* w2p = (const float2*)w2s + lane;
    const float* z0p = z1s[warp * 4 + 0];
    const float* z1p = z1s[warp * 4 + 1];
    const float* z2p = z1s[warp * 4 + 2];
    const float* z3p = z1s[warp * 4 + 3];
    #pragma unroll 8
    for (int f1 = 0; f1 < 64; f1++) {
        const float2 w = w2p[f1 * 32];
        const float za = z0p[f1], zb = z1p[f1], zc = z2p[f1], zd = z3p[f1];
        a0.x = fmaf(za, w.x, a0.x); a0.y = fmaf(za, w.y, a0.y);
        a1.x = fmaf(zb, w.x, a1.x); a1.y = fmaf(zb, w.y, a1.y);
        a2.x = fmaf(zc, w.x, a2.x); a2.y = fmaf(zc, w.y, a2.y);
        a3.x = fmaf(zd, w.x, a3.x); a3.y = fmaf(zd, w.y, a3.y);
    }

    const float w3a = w3s[2 * lane], w3b = w3s[2 * lane + 1];
    float s0 = fmaf(elu1(a0.x), w3a, elu1(a0.y) * w3b);
    float s1 = fmaf(elu1(a1.x), w3a, elu1(a1.y) * w3b);
    float s2 = fmaf(elu1(a2.x), w3a, elu1(a2.y) * w3b);
    float s3 = fmaf(elu1(a3.x), w3a, elu1(a3.y) * w3b);
    #pragma unroll
    for (int o = 16; o > 0; o >>= 1) {
        s0 += __shfl_down_sync(0xFFFFFFFFu, s0, o);
        s1 += __shfl_down_sync(0xFFFFFFFFu, s1, o);
        s2 += __shfl_down_sync(0xFFFFFFFFu, s2, o);
        s3 += __shfl_down_sync(0xFFFFFFFFu, s3, o);
    }
    if (lane == 0) wsum[warp] = elu1(s0) + elu1(s1) + elu1(s2) + elu1(s3);
    __syncthreads();

    if (tid == 0) {
        float s = 0.f;
        #pragma unroll
        for (int wv = 0; wv < 8; wv++) s += wsum[wv];
        atomicAdd(&g_acc[2], (double)s);
        atomicAdd(&g_acc[0], (double)rsum[0]);
        atomicAdd(&g_acc[1], (double)rsum[1]);
        __threadfence();
        const unsigned int done = atomicAdd(&g_done, 1u);
        if (done == gridDim.x - 1) {
            const double t0 = atomicAdd(&g_acc[0], 0.0);
            const double t1 = atomicAdd(&g_acc[1], 0.0);
            const double t2 = atomicAdd(&g_acc[2], 0.0);
            out[0] = (float)(t2 / (double)NTOK
                             - (double)regu2[0] * t0
                             - (double)regu[0] * t1);
        }
    }
}

// ---------------------------------------------------------------------------
// kernel_launch   d_in: 0=x 1=W1 2=W2 3=W3 4=regu2 5=regu 6=regu_length
// ---------------------------------------------------------------------------
extern "C" void kernel_launch(void* const* d_in, const int* in_sizes, int n_in,
                              void* d_out, int out_size) {
    const float* x  = (const float*)d_in[0];
    const float* W1 = (const float*)d_in[1];
    const float* W2 = (const float*)d_in[2];
    const float* W3 = (const float*)d_in[3];
    const float* r2 = (const float*)d_in[4];
    const float* r  = (const float*)d_in[5];
    const float* rl = (const float*)d_in[6];
    float* out = (float*)d_out;

    static const int smem_bytes = (6 * BANDLEN + 16) * sizeof(float);   // 56128
    cudaFuncSetAttribute(gemm_kernel, cudaFuncAttributeMaxDynamicSharedMemorySize, smem_bytes);

    w1prep_kernel<<<512, 128>>>(W1);      // also zeroes g_acc / g_done
    gemm_kernel<<<128, 256, smem_bytes>>>(x);
    mlp_kernel<<<256, 256>>>(x, W2, W3, r2, r, rl, out);
}

// round 8
// speedup vs baseline: 1.0543x; 1.0543x over previous
#include <cuda_runtime.h>
#include <cuda_bf16.h>
#include <cstdint>

// ============================================================================
//   x : (3, 8192) fp32   W1 : (8192, 64)   W2 : (64, 64)   W3 : (64, 1)
//   out = mean(per_row MLP(corr)) - regu2*sum(x2) - regu*sum(exp(x2/(2 rl^2)))
//   corr[i,j] = sum_c x[c,(i+j)%N] * x[c,i]
//
//   R8: gemm 512 thr/CTA (16 warps/SM, 4/SMSP) for latency hiding;
//   i-tile 512 rows x K-eighth 1024; branchless odd-copy staging.
// ============================================================================
#define NTOK 8192
#define KEIGHTH 1024
#define BANDLEN 1568                     // 1024 + 512 + slack, mult of 32
#define ODD_OFF (3 * BANDLEN + 16)       // +16 floats: disjoint banks vs even

__device__ double g_acc[3];                               // sum_x2, sum_exp, sum_per_row
__device__ unsigned int g_done;                           // mlp completion counter
__device__ __align__(16) float g_partial[8 * NTOK * 64];  // [ke][row][f], 16MB
__device__ __align__(16) uint32_t g_w1p[512 * 32 * 16];   // [ks][lane][nt*2+r] bf16x2

__device__ __forceinline__ uint32_t pack_bf16x2(float lo, float hi) {
    uint32_t r;
    asm("cvt.rn.bf16x2.f32 %0, %1, %2;" : "=r"(r) : "f"(hi), "f"(lo));
    return r;
}
__device__ __forceinline__ uint64_t pack2f(float v) {
    uint64_t r;
    asm("mov.b64 %0, {%1, %1};" : "=l"(r) : "f"(v));
    return r;
}
// (x0,x1,x2 broadcast-packed) . (u,v,w packed pairs) -> bf16x2(lo,hi)
__device__ __forceinline__ uint32_t dot3cvt(uint64_t x0, uint64_t x1, uint64_t x2,
                                            uint64_t u, uint64_t v, uint64_t w) {
    uint32_t out;
    asm("{\n\t"
        ".reg .b64 t;\n\t"
        ".reg .b32 lo, hi;\n\t"
        "mul.rn.f32x2 t, %3, %6;\n\t"
        "fma.rn.f32x2 t, %2, %5, t;\n\t"
        "fma.rn.f32x2 t, %1, %4, t;\n\t"
        "mov.b64 {lo, hi}, t;\n\t"
        "cvt.rn.bf16x2.f32 %0, hi, lo;\n\t"
        "}"
        : "=r"(out)
        : "l"(x0), "l"(x1), "l"(x2), "l"(u), "l"(v), "l"(w));
    return out;
}
__device__ __forceinline__ float elu1(float v) { return v > 0.f ? v : expm1f(v); }

#define MMA_BF16(d0,d1,d2,d3,a0,a1,a2,a3,b0,b1) \
    asm volatile("mma.sync.aligned.m16n8k16.row.col.f32.bf16.bf16.f32 " \
                 "{%0,%1,%2,%3}, {%4,%5,%6,%7}, {%8,%9}, {%0,%1,%2,%3};" \
                 : "+f"(d0), "+f"(d1), "+f"(d2), "+f"(d3) \
                 : "r"(a0), "r"(a1), "r"(a2), "r"(a3), "r"(b0), "r"(b1))

// ---------------------------------------------------------------------------
// K1: W1 -> m16n8k16 B fragments. 512 blocks x 128 thr, 1 k-step per block.
// ---------------------------------------------------------------------------
__global__ __launch_bounds__(128) void w1prep_kernel(const float* __restrict__ W1) {
    __shared__ float w[1024];
    if (blockIdx.x == 0 && threadIdx.x == 0) {
        g_acc[0] = 0.0; g_acc[1] = 0.0; g_acc[2] = 0.0; g_done = 0u;
    }
    const int b = blockIdx.x, tid = threadIdx.x;
    const float4* src = (const float4*)(W1 + b * 1024);   // k-rows [16b,16b+16) x 64
    ((float4*)w)[tid]       = src[tid];
    ((float4*)w)[tid + 128] = src[tid + 128];
    __syncthreads();

    uint32_t o4[4];
    #pragma unroll
    for (int j = 0; j < 4; j++) {
        const int o = tid * 4 + j;                        // 0..511
        const int lane = o >> 4;
        const int q = o & 15;
        const int nt = q >> 1, r = q & 1;
        const int k = (lane & 3) * 2 + r * 8;
        const int n = nt * 8 + (lane >> 2);
        o4[j] = pack_bf16x2(w[k * 64 + n], w[(k + 1) * 64 + n]);
    }
    ((uint4*)g_w1p)[b * 128 + tid] = make_uint4(o4[0], o4[1], o4[2], o4[3]);
}

// ---------------------------------------------------------------------------
// K2: fused corr-build (f32x2) + mma.sync bf16 GEMM (preact = corr @ W1)
//   grid = 128: (i-tile of 512 rows) x (K-eighth of 1024); 512 thr (16 warps)
// ---------------------------------------------------------------------------
__global__ __launch_bounds__(512, 1) void gemm_kernel(const float* __restrict__ x) {
    extern __shared__ float band[];                   // even[3][BANDLEN] | pad16 | odd[3][BANDLEN]
    const int tid = threadIdx.x, warp = tid >> 5, lane = tid & 31;
    const int g = lane >> 2, t = lane & 3;
    const int it = blockIdx.x >> 3, ke = blockIdx.x & 7;
    const int i0 = it * 512, jbase = ke * KEIGHTH;

    // stage: even[o]=x[base+o]; odd[o-1]=even[o] (o=0 write lands in pad gap)
    for (int o = tid; o < BANDLEN; o += 512) {
        const int s0 = (i0 + jbase + o) & (NTOK - 1);
        const float v0 = x[s0], v1 = x[NTOK + s0], v2 = x[2 * NTOK + s0];
        band[o]               = v0;
        band[BANDLEN + o]     = v1;
        band[2 * BANDLEN + o] = v2;
        band[ODD_OFF + o - 1]               = v0;
        band[ODD_OFF + BANDLEN + o - 1]     = v1;
        band[ODD_OFF + 2 * BANDLEN + o - 1] = v2;
    }

    // per-thread row scalars, broadcast-packed for f32x2
    const int r0 = i0 + warp * 32 + g;
    const uint64_t xA0 = pack2f(x[r0]),      xA1 = pack2f(x[NTOK + r0]),      xA2 = pack2f(x[2 * NTOK + r0]);
    const uint64_t xB0 = pack2f(x[r0 + 8]),  xB1 = pack2f(x[NTOK + r0 + 8]),  xB2 = pack2f(x[2 * NTOK + r0 + 8]);
    const uint64_t xC0 = pack2f(x[r0 + 16]), xC1 = pack2f(x[NTOK + r0 + 16]), xC2 = pack2f(x[2 * NTOK + r0 + 16]);
    const uint64_t xD0 = pack2f(x[r0 + 24]), xD1 = pack2f(x[NTOK + r0 + 24]), xD2 = pack2f(x[2 * NTOK + r0 + 24]);
    __syncthreads();

    // parity-corrected aligned pair pointers (each uint64 = 2 adjacent floats)
    const int par = g & 1;
    const int ib = (warp * 32 + g + 2 * t - par) >> 1;    // uint64 index
    const uint64_t* sb = (const uint64_t*)(band + (par ? ODD_OFF : 0));
    const uint64_t* p0 = sb + ib;
    const uint64_t* p1 = sb + (BANDLEN >> 1) + ib;
    const uint64_t* p2 = sb + BANDLEN + ib;

    const uint4* bp = (const uint4*)g_w1p + (size_t)(ke * 64) * 128 + lane * 4;

    float acc[2][8][4];
    #pragma unroll
    for (int s = 0; s < 2; s++)
        #pragma unroll
        for (int nt = 0; nt < 8; nt++)
            #pragma unroll
            for (int k = 0; k < 4; k++) acc[s][nt][k] = 0.f;

    // carried pairs at step offsets +0,+8,+16 per channel
    uint64_t u0 = p0[0], u1 = p0[4], u2 = p0[8];
    uint64_t v0 = p1[0], v1 = p1[4], v2 = p1[8];
    uint64_t w0 = p2[0], w1 = p2[4], w2 = p2[8];

    #pragma unroll 2
    for (int ks = 0; ks < 64; ks++) {
        const int e = ks * 8;
        const uint64_t u3 = p0[e + 12], u4 = p0[e + 16];  // fresh +24, +32
        const uint64_t v3 = p1[e + 12], v4 = p1[e + 16];
        const uint64_t w3 = p2[e + 12], w4 = p2[e + 16];

        const uint32_t a0 = dot3cvt(xA0, xA1, xA2, u0, v0, w0);   // (g,    k=2t)
        const uint32_t a2 = dot3cvt(xA0, xA1, xA2, u1, v1, w1);   // (g,    k=2t+8)
        const uint32_t a1 = dot3cvt(xB0, xB1, xB2, u1, v1, w1);   // (g+8,  k=2t)
        const uint32_t a3 = dot3cvt(xB0, xB1, xB2, u2, v2, w2);   // (g+8,  k=2t+8)
        const uint32_t c0 = dot3cvt(xC0, xC1, xC2, u2, v2, w2);   // (g+16, k=2t)
        const uint32_t c2 = dot3cvt(xC0, xC1, xC2, u3, v3, w3);   // (g+16, k=2t+8)
        const uint32_t c1 = dot3cvt(xD0, xD1, xD2, u3, v3, w3);   // (g+24, k=2t)
        const uint32_t c3 = dot3cvt(xD0, xD1, xD2, u4, v4, w4);   // (g+24, k=2t+8)

        const uint4 B0 = bp[0], B1 = bp[1], B2 = bp[2], B3 = bp[3];
        bp += 128;

        MMA_BF16(acc[0][0][0], acc[0][0][1], acc[0][0][2], acc[0][0][3], a0, a1, a2, a3, B0.x, B0.y);
        MMA_BF16(acc[0][1][0], acc[0][1][1], acc[0][1][2], acc[0][1][3], a0, a1, a2, a3, B0.z, B0.w);
        MMA_BF16(acc[0][2][0], acc[0][2][1], acc[0][2][2], acc[0][2][3], a0, a1, a2, a3, B1.x, B1.y);
        MMA_BF16(acc[0][3][0], acc[0][3][1], acc[0][3][2], acc[0][3][3], a0, a1, a2, a3, B1.z, B1.w);
        MMA_BF16(acc[0][4][0], acc[0][4][1], acc[0][4][2], acc[0][4][3], a0, a1, a2, a3, B2.x, B2.y);
        MMA_BF16(acc[0][5][0], acc[0][5][1], acc[0][5][2], acc[0][5][3], a0, a1, a2, a3, B2.z, B2.w);
        MMA_BF16(acc[0][6][0], acc[0][6][1], acc[0][6][2], acc[0][6][3], a0, a1, a2, a3, B3.x, B3.y);
        MMA_BF16(acc[0][7][0], acc[0][7][1], acc[0][7][2], acc[0][7][3], a0, a1, a2, a3, B3.z, B3.w);

        MMA_BF16(acc[1][0][0], acc[1][0][1], acc[1][0][2], acc[1][0][3], c0, c1, c2, c3, B0.x, B0.y);
        MMA_BF16(acc[1][1][0], acc[1][1][1], acc[1][1][2], acc[1][1][3], c0, c1, c2, c3, B0.z, B0.w);
        MMA_BF16(acc[1][2][0], acc[1][2][1], acc[1][2][2], acc[1][2][3], c0, c1, c2, c3, B1.x, B1.y);
        MMA_BF16(acc[1][3][0], acc[1][3][1], acc[1][3][2], acc[1][3][3], c0, c1, c2, c3, B1.z, B1.w);
        MMA_BF16(acc[1][4][0], acc[1][4][1], acc[1][4][2], acc[1][4][3], c0, c1, c2, c3, B2.x, B2.y);
        MMA_BF16(acc[1][5][0], acc[1][5][1], acc[1][5][2], acc[1][5][3], c0, c1, c2, c3, B2.z, B2.w);
        MMA_BF16(acc[1][6][0], acc[1][6][1], acc[1][6][2], acc[1][6][3], c0, c1, c2, c3, B3.x, B3.y);
        MMA_BF16(acc[1][7][0], acc[1][7][1], acc[1][7][2], acc[1][7][3], c0, c1, c2, c3, B3.z, B3.w);

        u0 = u2; u1 = u3; u2 = u4;
        v0 = v2; v1 = v3; v2 = v4;
        w0 = w2; w1 = w3; w2 = w4;
    }

    // epilogue: [ke][row][f] layout; quad-contiguous 32B-sector float2 stores
    float* basep = g_partial + (size_t)ke * (NTOK * 64);
    #pragma unroll
    for (int s = 0; s < 2; s++) {
        const int rA = r0 + 16 * s, rB = rA + 8;
        #pragma unroll
        for (int nt = 0; nt < 8; nt++) {
            const int n = nt * 8 + 2 * t;
            *(float2*)(basep + (size_t)rA * 64 + n) = make_float2(acc[s][nt][0], acc[s][nt][1]);
            *(float2*)(basep + (size_t)rB * 64 + n) = make_float2(acc[s][nt][2], acc[s][nt][3]);
        }
    }
}

// ---------------------------------------------------------------------------
// K3: MLP epilogue + regularization + final combine.
//   grid = 256 CTAs x 256 thr. Block owns 32 rows; warp owns 4 rows fused.
// ---------------------------------------------------------------------------
__global__ __launch_bounds__(256) void mlp_kernel(const float* __restrict__ x,
                                                  const float* __restrict__ W2,
                                                  const float* __restrict__ W3,
                                                  const float* __restrict__ regu2,
                                                  const float* __restrict__ regu,
                                                  const float* __restrict__ rl_p,
                                                  float* __restrict__ out) {
    __shared__ float w2s[4096];
    __shared__ float w3s[64];
    __shared__ float z1s[32][64];
    __shared__ float wsum[8];
    __shared__ float rsum[2];
    const int tid = threadIdx.x, warp = tid >> 5, lane = tid & 31;

    if (warp == 0) {
        const int tok = blockIdx.x * 32 + lane;
        const float a = x[tok], b = x[NTOK + tok], c = x[2 * NTOK + tok];
        float x2 = fmaf(a, a, fmaf(b, b, c * c));
        const float rl = rl_p[0];
        float e = expf(x2 / (2.f * rl * rl));
        #pragma unroll
        for (int o = 16; o > 0; o >>= 1) {
            x2 += __shfl_down_sync(0xFFFFFFFFu, x2, o);
            e  += __shfl_down_sync(0xFFFFFFFFu, e, o);
        }
        if (lane == 0) { rsum[0] = x2; rsum[1] = e; }
    }

    for (int tv = tid; tv < 4096; tv += 256) w2s[tv] = W2[tv];
    if (tid < 64) w3s[tid] = W3[tid];

    // preacts: per row, 8 independent float2 loads (one per K-eighth), sum
    const int rbase = blockIdx.x * 32 + warp * 4;
    #pragma unroll
    for (int rr = 0; rr < 4; rr++) {
        float2 tq[8];
        #pragma unroll
        for (int q = 0; q < 8; q++)
            tq[q] = ((const float2*)(g_partial + ((size_t)q * NTOK + rbase + rr) * 64))[lane];
        float px = 0.f, py = 0.f;
        #pragma unroll
        for (int q = 0; q < 8; q++) { px += tq[q].x; py += tq[q].y; }
        z1s[warp * 4 + rr][2 * lane]     = elu1(px);
        z1s[warp * 4 + rr][2 * lane + 1] = elu1(py);
    }
    __syncthreads();

    float2 a0 = make_float2(0.f, 0.f), a1 = a0, a2 = a0, a3 = a0;
    const float2* w2p = (const float2*)w2s + lane;
    const float* z0p = z1s[warp * 4 + 0];
    const float* z1p = z1s[warp * 4 + 1];
    const float* z2p = z1s[warp * 4 + 2];
    const float* z3p = z1s[warp * 4 + 3];
    #pragma unroll 8
    for (int f1 = 0; f1 < 64; f1++) {
        const float2 w = w2p[f1 * 32];
        const float za = z0p[f1], zb = z1p[f1], zc = z2p[f1], zd = z3p[f1];
        a0.x = fmaf(za, w.x, a0.x); a0.y = fmaf(za, w.y, a0.y);
        a1.x = fmaf(zb, w.x, a1.x); a1.y = fmaf(zb, w.y, a1.y);
        a2.x = fmaf(zc, w.x, a2.x); a2.y = fmaf(zc, w.y, a2.y);
        a3.x = fmaf(zd, w.x, a3.x); a3.y = fmaf(zd, w.y, a3.y);
    }

    const float w3a = w3s[2 * lane], w3b = w3s[2 * lane + 1];
    float s0 = fmaf(elu1(a0.x), w3a, elu1(a0.y) * w3b);
    float s1 = fmaf(elu1(a1.x), w3a, elu1(a1.y) * w3b);
    float s2 = fmaf(elu1(a2.x), w3a, elu1(a2.y) * w3b);
    float s3 = fmaf(elu1(a3.x), w3a, elu1(a3.y) * w3b);
    #pragma unroll
    for (int o = 16; o > 0; o >>= 1) {
        s0 += __shfl_down_sync(0xFFFFFFFFu, s0, o);
        s1 += __shfl_down_sync(0xFFFFFFFFu, s1, o);
        s2 += __shfl_down_sync(0xFFFFFFFFu, s2, o);
        s3 += __shfl_down_sync(0xFFFFFFFFu, s3, o);
    }
    if (lane == 0) wsum[warp] = elu1(s0) + elu1(s1) + elu1(s2) + elu1(s3);
    __syncthreads();

    if (tid == 0) {
        float s = 0.f;
        #pragma unroll
        for (int wv = 0; wv < 8; wv++) s += wsum[wv];
        atomicAdd(&g_acc[2], (double)s);
        atomicAdd(&g_acc[0], (double)rsum[0]);
        atomicAdd(&g_acc[1], (double)rsum[1]);
        __threadfence();
        const unsigned int done = atomicAdd(&g_done, 1u);
        if (done == gridDim.x - 1) {
            const double t0 = atomicAdd(&g_acc[0], 0.0);
            const double t1 = atomicAdd(&g_acc[1], 0.0);
            const double t2 = atomicAdd(&g_acc[2], 0.0);
            out[0] = (float)(t2 / (double)NTOK
                             - (double)regu2[0] * t0
                             - (double)regu[0] * t1);
        }
    }
}

// ---------------------------------------------------------------------------
// kernel_launch   d_in: 0=x 1=W1 2=W2 3=W3 4=regu2 5=regu 6=regu_length
// ---------------------------------------------------------------------------
extern "C" void kernel_launch(void* const* d_in, const int* in_sizes, int n_in,
                              void* d_out, int out_size) {
    const float* x  = (const float*)d_in[0];
    const float* W1 = (const float*)d_in[1];
    const float* W2 = (const float*)d_in[2];
    const float* W3 = (const float*)d_in[3];
    const float* r2 = (const float*)d_in[4];
    const float* r  = (const float*)d_in[5];
    const float* rl = (const float*)d_in[6];
    float* out = (float*)d_out;

    static const int smem_bytes = (6 * BANDLEN + 16) * sizeof(float);   // 37696
    cudaFuncSetAttribute(gemm_kernel, cudaFuncAttributeMaxDynamicSharedMemorySize, smem_bytes);

    w1prep_kernel<<<512, 128>>>(W1);      // also zeroes g_acc / g_done
    gemm_kernel<<<128, 512, smem_bytes>>>(x);
    mlp_kernel<<<256, 256>>>(x, W2, W3, r2, r, rl, out);
}

// round 9
// speedup vs baseline: 1.0964x; 1.0399x over previous
#include <cuda_runtime.h>
#include <cuda_bf16.h>
#include <cstdint>

// ============================================================================
//   x : (3, 8192) fp32   W1 : (8192, 64)   W2 : (64, 64)   W3 : (64, 1)
//   out = mean(per_row MLP(corr)) - regu2*sum(x2) - regu*sum(exp(x2/(2 rl^2)))
//   corr[i,j] = sum_c x[c,(i+j)%N] * x[c,i]
//
//   R9: single persistent fused kernel (128 CTAs, all co-resident):
//   phase0 W1-frag prep + staging | grid barrier | phase1 corr+MMA gemm |
//   grid barrier | phase2 warp-per-row MLP + reductions + final combine.
// ============================================================================
#define NTOK 8192
#define KEIGHTH 1024
#define BANDLEN 1568                     // 1024 + 512 + slack, mult of 32
#define ODD_OFF (3 * BANDLEN + 16)       // +16 floats: disjoint banks vs even
#define NCTA 128u

__device__ double g_acc[3];                               // sum_x2, sum_exp, sum_per_row
__device__ unsigned int g_done;                           // completion counter
__device__ unsigned int g_bar;                            // grid barrier counter
__device__ __align__(16) float g_partial[8 * NTOK * 64];  // [ke][row][f], 16MB
__device__ __align__(16) uint32_t g_w1p[512 * 32 * 16];   // [ks][lane][nt*2+r] bf16x2

__device__ __forceinline__ uint32_t pack_bf16x2(float lo, float hi) {
    uint32_t r;
    asm("cvt.rn.bf16x2.f32 %0, %1, %2;" : "=r"(r) : "f"(hi), "f"(lo));
    return r;
}
__device__ __forceinline__ uint64_t pack2f(float v) {
    uint64_t r;
    asm("mov.b64 %0, {%1, %1};" : "=l"(r) : "f"(v));
    return r;
}
__device__ __forceinline__ uint32_t dot3cvt(uint64_t x0, uint64_t x1, uint64_t x2,
                                            uint64_t u, uint64_t v, uint64_t w) {
    uint32_t out;
    asm("{\n\t"
        ".reg .b64 t;\n\t"
        ".reg .b32 lo, hi;\n\t"
        "mul.rn.f32x2 t, %3, %6;\n\t"
        "fma.rn.f32x2 t, %2, %5, t;\n\t"
        "fma.rn.f32x2 t, %1, %4, t;\n\t"
        "mov.b64 {lo, hi}, t;\n\t"
        "cvt.rn.bf16x2.f32 %0, hi, lo;\n\t"
        "}"
        : "=r"(out)
        : "l"(x0), "l"(x1), "l"(x2), "l"(u), "l"(v), "l"(w));
    return out;
}
__device__ __forceinline__ float elu1(float v) { return v > 0.f ? v : expm1f(v); }

#define MMA_BF16(d0,d1,d2,d3,a0,a1,a2,a3,b0,b1) \
    asm volatile("mma.sync.aligned.m16n8k16.row.col.f32.bf16.bf16.f32 " \
                 "{%0,%1,%2,%3}, {%4,%5,%6,%7}, {%8,%9}, {%0,%1,%2,%3};" \
                 : "+f"(d0), "+f"(d1), "+f"(d2), "+f"(d3) \
                 : "r"(a0), "r"(a1), "r"(a2), "r"(a3), "r"(b0), "r"(b1))

// Software grid barrier: all 128 CTAs are co-resident (1 CTA/SM, grid<=SMs).
__device__ __forceinline__ void grid_bar(unsigned target) {
    __syncthreads();
    if (threadIdx.x == 0) {
        __threadfence();
        atomicAdd(&g_bar, 1u);
        while (*((volatile unsigned*)&g_bar) < target) {}
        __threadfence();
    }
    __syncthreads();
}

// ---------------------------------------------------------------------------
// Fused kernel. grid = 128 x 512 threads.
//   SMEM: band[9424] | w2s[4096] | z1s[4096] | w3s[64] | wsum[16] | rsum[2]
// ---------------------------------------------------------------------------
__global__ __launch_bounds__(512, 1) void fused_kernel(
        const float* __restrict__ x,  const float* __restrict__ W1,
        const float* __restrict__ W2, const float* __restrict__ W3,
        const float* __restrict__ regu2, const float* __restrict__ regu,
        const float* __restrict__ rl_p, float* __restrict__ out) {
    extern __shared__ float smem[];
    float* band = smem;                          // 9424 floats
    float* w2s  = smem + 9424;                   // 4096
    float* z1s  = smem + 9424 + 4096;            // 4096 ([64 rows][64 f])
    float* w3s  = z1s + 4096;                    // 64
    float* wsum = w3s + 64;                      // 16
    float* rsum = wsum + 16;                     // 2

    const int tid = threadIdx.x, warp = tid >> 5, lane = tid & 31;
    const int g = lane >> 2, t = lane & 3;
    const int b = blockIdx.x;
    const int it = b >> 3, ke = b & 7;
    const int i0 = it * 512, jbase = ke * KEIGHTH;

    if (b == 0 && tid == 0) { g_acc[0] = 0.0; g_acc[1] = 0.0; g_acc[2] = 0.0; }

    // ---- Phase 0a: stage band (even + shifted odd copy; o=0 lands in pad) ----
    for (int o = tid; o < BANDLEN; o += 512) {
        const int s0 = (i0 + jbase + o) & (NTOK - 1);
        const float v0 = x[s0], v1 = x[NTOK + s0], v2 = x[2 * NTOK + s0];
        band[o]               = v0;
        band[BANDLEN + o]     = v1;
        band[2 * BANDLEN + o] = v2;
        band[ODD_OFF + o - 1]               = v0;
        band[ODD_OFF + BANDLEN + o - 1]     = v1;
        band[ODD_OFF + 2 * BANDLEN + o - 1] = v2;
    }

    // ---- Phase 0b: W1 fragment prep for this CTA's 4 k-steps (64 k-rows) ----
    {
        const float4* src = (const float4*)(W1 + b * 4096);   // 64 rows x 64
        float4* w4 = (float4*)w2s;
        w4[tid]       = src[tid];
        w4[tid + 512] = src[tid + 512];
        __syncthreads();
        const int ksl = tid >> 7, inner = tid & 127;
        uint32_t o4[4];
        #pragma unroll
        for (int j = 0; j < 4; j++) {
            const int o = inner * 4 + j;                      // 0..511
            const int ln = o >> 4;
            const int q = o & 15;
            const int nt = q >> 1, r = q & 1;
            const int k = ksl * 16 + (ln & 3) * 2 + r * 8;
            const int n = nt * 8 + (ln >> 2);
            o4[j] = pack_bf16x2(w2s[k * 64 + n], w2s[(k + 1) * 64 + n]);
        }
        ((uint4*)g_w1p)[b * 512 + tid] = make_uint4(o4[0], o4[1], o4[2], o4[3]);
        __syncthreads();
    }

    // ---- Phase 0c: stage W2/W3; reg sums for this CTA's 64 tokens (warp 0) ----
    #pragma unroll
    for (int tv = tid; tv < 4096; tv += 512) w2s[tv] = W2[tv];
    if (tid < 64) w3s[tid] = W3[tid];
    if (warp == 0) {
        float x2t = 0.f, et = 0.f;
        const float rl = rl_p[0];
        const float inv = 1.f / (2.f * rl * rl);
        #pragma unroll
        for (int k = 0; k < 2; k++) {
            const int tok = b * 64 + k * 32 + lane;
            const float a = x[tok], bb = x[NTOK + tok], c = x[2 * NTOK + tok];
            const float x2 = fmaf(a, a, fmaf(bb, bb, c * c));
            x2t += x2;
            et  += expf(x2 * inv);
        }
        #pragma unroll
        for (int o = 16; o > 0; o >>= 1) {
            x2t += __shfl_down_sync(0xFFFFFFFFu, x2t, o);
            et  += __shfl_down_sync(0xFFFFFFFFu, et, o);
        }
        if (lane == 0) { rsum[0] = x2t; rsum[1] = et; }
    }

    // per-thread row scalars for gemm, broadcast-packed
    const int r0 = i0 + warp * 32 + g;
    const uint64_t xA0 = pack2f(x[r0]),      xA1 = pack2f(x[NTOK + r0]),      xA2 = pack2f(x[2 * NTOK + r0]);
    const uint64_t xB0 = pack2f(x[r0 + 8]),  xB1 = pack2f(x[NTOK + r0 + 8]),  xB2 = pack2f(x[2 * NTOK + r0 + 8]);
    const uint64_t xC0 = pack2f(x[r0 + 16]), xC1 = pack2f(x[NTOK + r0 + 16]), xC2 = pack2f(x[2 * NTOK + r0 + 16]);
    const uint64_t xD0 = pack2f(x[r0 + 24]), xD1 = pack2f(x[NTOK + r0 + 24]), xD2 = pack2f(x[2 * NTOK + r0 + 24]);

    // ---- grid barrier 1: all g_w1p fragments written ----
    grid_bar(NCTA);

    // ---- Phase 1: corr-build + MMA mainloop (identical to R8) ----
    const int par = g & 1;
    const int ib = (warp * 32 + g + 2 * t - par) >> 1;
    const uint64_t* sb = (const uint64_t*)(band + (par ? ODD_OFF : 0));
    const uint64_t* p0 = sb + ib;
    const uint64_t* p1 = sb + (BANDLEN >> 1) + ib;
    const uint64_t* p2 = sb + BANDLEN + ib;

    const uint4* bp = (const uint4*)g_w1p + (size_t)(ke * 64) * 128 + lane * 4;

    float acc[2][8][4];
    #pragma unroll
    for (int s = 0; s < 2; s++)
        #pragma unroll
        for (int nt = 0; nt < 8; nt++)
            #pragma unroll
            for (int k = 0; k < 4; k++) acc[s][nt][k] = 0.f;

    uint64_t u0 = p0[0], u1 = p0[4], u2 = p0[8];
    uint64_t v0 = p1[0], v1 = p1[4], v2 = p1[8];
    uint64_t w0 = p2[0], w1 = p2[4], w2 = p2[8];

    #pragma unroll 2
    for (int ks = 0; ks < 64; ks++) {
        const int e = ks * 8;
        const uint64_t u3 = p0[e + 12], u4 = p0[e + 16];
        const uint64_t v3 = p1[e + 12], v4 = p1[e + 16];
        const uint64_t w3 = p2[e + 12], w4 = p2[e + 16];

        const uint32_t a0 = dot3cvt(xA0, xA1, xA2, u0, v0, w0);
        const uint32_t a2 = dot3cvt(xA0, xA1, xA2, u1, v1, w1);
        const uint32_t a1 = dot3cvt(xB0, xB1, xB2, u1, v1, w1);
        const uint32_t a3 = dot3cvt(xB0, xB1, xB2, u2, v2, w2);
        const uint32_t c0 = dot3cvt(xC0, xC1, xC2, u2, v2, w2);
        const uint32_t c2 = dot3cvt(xC0, xC1, xC2, u3, v3, w3);
        const uint32_t c1 = dot3cvt(xD0, xD1, xD2, u3, v3, w3);
        const uint32_t c3 = dot3cvt(xD0, xD1, xD2, u4, v4, w4);

        const uint4 B0 = bp[0], B1 = bp[1], B2 = bp[2], B3 = bp[3];
        bp += 128;

        MMA_BF16(acc[0][0][0], acc[0][0][1], acc[0][0][2], acc[0][0][3], a0, a1, a2, a3, B0.x, B0.y);
        MMA_BF16(acc[0][1][0], acc[0][1][1], acc[0][1][2], acc[0][1][3], a0, a1, a2, a3, B0.z, B0.w);
        MMA_BF16(acc[0][2][0], acc[0][2][1], acc[0][2][2], acc[0][2][3], a0, a1, a2, a3, B1.x, B1.y);
        MMA_BF16(acc[0][3][0], acc[0][3][1], acc[0][3][2], acc[0][3][3], a0, a1, a2, a3, B1.z, B1.w);
        MMA_BF16(acc[0][4][0], acc[0][4][1], acc[0][4][2], acc[0][4][3], a0, a1, a2, a3, B2.x, B2.y);
        MMA_BF16(acc[0][5][0], acc[0][5][1], acc[0][5][2], acc[0][5][3], a0, a1, a2, a3, B2.z, B2.w);
        MMA_BF16(acc[0][6][0], acc[0][6][1], acc[0][6][2], acc[0][6][3], a0, a1, a2, a3, B3.x, B3.y);
        MMA_BF16(acc[0][7][0], acc[0][7][1], acc[0][7][2], acc[0][7][3], a0, a1, a2, a3, B3.z, B3.w);

        MMA_BF16(acc[1][0][0], acc[1][0][1], acc[1][0][2], acc[1][0][3], c0, c1, c2, c3, B0.x, B0.y);
        MMA_BF16(acc[1][1][0], acc[1][1][1], acc[1][1][2], acc[1][1][3], c0, c1, c2, c3, B0.z, B0.w);
        MMA_BF16(acc[1][2][0], acc[1][2][1], acc[1][2][2], acc[1][2][3], c0, c1, c2, c3, B1.x, B1.y);
        MMA_BF16(acc[1][3][0], acc[1][3][1], acc[1][3][2], acc[1][3][3], c0, c1, c2, c3, B1.z, B1.w);
        MMA_BF16(acc[1][4][0], acc[1][4][1], acc[1][4][2], acc[1][4][3], c0, c1, c2, c3, B2.x, B2.y);
        MMA_BF16(acc[1][5][0], acc[1][5][1], acc[1][5][2], acc[1][5][3], c0, c1, c2, c3, B2.z, B2.w);
        MMA_BF16(acc[1][6][0], acc[1][6][1], acc[1][6][2], acc[1][6][3], c0, c1, c2, c3, B3.x, B3.y);
        MMA_BF16(acc[1][7][0], acc[1][7][1], acc[1][7][2], acc[1][7][3], c0, c1, c2, c3, B3.z, B3.w);

        u0 = u2; u1 = u3; u2 = u4;
        v0 = v2; v1 = v3; v2 = v4;
        w0 = w2; w1 = w3; w2 = w4;
    }

    // epilogue: [ke][row][f]; quad-contiguous float2 stores
    {
        float* basep = g_partial + (size_t)ke * (NTOK * 64);
        #pragma unroll
        for (int s = 0; s < 2; s++) {
            const int rA = r0 + 16 * s, rB = rA + 8;
            #pragma unroll
            for (int nt = 0; nt < 8; nt++) {
                const int n = nt * 8 + 2 * t;
                *(float2*)(basep + (size_t)rA * 64 + n) = make_float2(acc[s][nt][0], acc[s][nt][1]);
                *(float2*)(basep + (size_t)rB * 64 + n) = make_float2(acc[s][nt][2], acc[s][nt][3]);
            }
        }
    }

    // ---- grid barrier 2: all g_partial written ----
    grid_bar(2 * NCTA);

    // ---- Phase 2: MLP for this CTA's 64 rows (16 warps x 4 rows) ----
    const int rbase = b * 64 + warp * 4;
    #pragma unroll
    for (int rr = 0; rr < 4; rr++) {
        float2 tq[8];
        #pragma unroll
        for (int q = 0; q < 8; q++)
            tq[q] = ((const float2*)(g_partial + ((size_t)q * NTOK + rbase + rr) * 64))[lane];
        float px = 0.f, py = 0.f;
        #pragma unroll
        for (int q = 0; q < 8; q++) { px += tq[q].x; py += tq[q].y; }
        z1s[(warp * 4 + rr) * 64 + 2 * lane]     = elu1(px);
        z1s[(warp * 4 + rr) * 64 + 2 * lane + 1] = elu1(py);
    }
    __syncwarp();

    float2 m0 = make_float2(0.f, 0.f), m1 = m0, m2 = m0, m3 = m0;
    const float2* w2p = (const float2*)w2s + lane;
    const float* z0p = z1s + (warp * 4 + 0) * 64;
    const float* z1p = z1s + (warp * 4 + 1) * 64;
    const float* z2p = z1s + (warp * 4 + 2) * 64;
    const float* z3p = z1s + (warp * 4 + 3) * 64;
    #pragma unroll 8
    for (int f1 = 0; f1 < 64; f1++) {
        const float2 w = w2p[f1 * 32];
        const float za = z0p[f1], zb = z1p[f1], zc = z2p[f1], zd = z3p[f1];
        m0.x = fmaf(za, w.x, m0.x); m0.y = fmaf(za, w.y, m0.y);
        m1.x = fmaf(zb, w.x, m1.x); m1.y = fmaf(zb, w.y, m1.y);
        m2.x = fmaf(zc, w.x, m2.x); m2.y = fmaf(zc, w.y, m2.y);
        m3.x = fmaf(zd, w.x, m3.x); m3.y = fmaf(zd, w.y, m3.y);
    }

    const float w3a = w3s[2 * lane], w3b = w3s[2 * lane + 1];
    float s0 = fmaf(elu1(m0.x), w3a, elu1(m0.y) * w3b);
    float s1 = fmaf(elu1(m1.x), w3a, elu1(m1.y) * w3b);
    float s2 = fmaf(elu1(m2.x), w3a, elu1(m2.y) * w3b);
    float s3 = fmaf(elu1(m3.x), w3a, elu1(m3.y) * w3b);
    #pragma unroll
    for (int o = 16; o > 0; o >>= 1) {
        s0 += __shfl_down_sync(0xFFFFFFFFu, s0, o);
        s1 += __shfl_down_sync(0xFFFFFFFFu, s1, o);
        s2 += __shfl_down_sync(0xFFFFFFFFu, s2, o);
        s3 += __shfl_down_sync(0xFFFFFFFFu, s3, o);
    }
    if (lane == 0) wsum[warp] = elu1(s0) + elu1(s1) + elu1(s2) + elu1(s3);
    __syncthreads();

    if (tid == 0) {
        float s = 0.f;
        #pragma unroll
        for (int wv = 0; wv < 16; wv++) s += wsum[wv];
        atomicAdd(&g_acc[2], (double)s);
        atomicAdd(&g_acc[0], (double)rsum[0]);
        atomicAdd(&g_acc[1], (double)rsum[1]);
        __threadfence();
        const unsigned int done = atomicAdd(&g_done, 1u);
        if (done == NCTA - 1u) {
            const double t0 = atomicAdd(&g_acc[0], 0.0);
            const double t1 = atomicAdd(&g_acc[1], 0.0);
            const double t2 = atomicAdd(&g_acc[2], 0.0);
            out[0] = (float)(t2 / (double)NTOK
                             - (double)regu2[0] * t0
                             - (double)regu[0] * t1);
            g_done = 0u;          // reset for the next graph replay
            g_bar  = 0u;
        }
    }
}

// ---------------------------------------------------------------------------
// kernel_launch   d_in: 0=x 1=W1 2=W2 3=W3 4=regu2 5=regu 6=regu_length
// ---------------------------------------------------------------------------
extern "C" void kernel_launch(void* const* d_in, const int* in_sizes, int n_in,
                              void* d_out, int out_size) {
    const float* x  = (const float*)d_in[0];
    const float* W1 = (const float*)d_in[1];
    const float* W2 = (const float*)d_in[2];
    const float* W3 = (const float*)d_in[3];
    const float* r2 = (const float*)d_in[4];
    const float* r  = (const float*)d_in[5];
    const float* rl = (const float*)d_in[6];
    float* out = (float*)d_out;

    static const int smem_bytes = (9424 + 4096 + 4096 + 64 + 16 + 2) * sizeof(float); // 70792
    cudaFuncSetAttribute(fused_kernel, cudaFuncAttributeMaxDynamicSharedMemorySize, smem_bytes);

    fused_kernel<<<128, 512, smem_bytes>>>(x, W1, W2, W3, r2, r, rl, out);
}

// round 10
// speedup vs baseline: 1.3031x; 1.1885x over previous
#include <cuda_runtime.h>
#include <cuda_fp16.h>
#include <cstdint>

// ============================================================================
//   x : (3, 8192) fp32   W1 : (8192, 64)   W2 : (64, 64)   W3 : (64, 1)
//   out = mean(per_row MLP(corr)) - regu2*sum(x2) - regu*sum(exp(x2/(2 rl^2)))
//   corr[i,j] = sum_c x[c,(i+j)%N] * x[c,i]
//
//   R10: coalesced B-frag layout [ks][j][lane]; fp16 A/B/acc MMA
//   (m16n8k16.f16); 64 rows/warp (2 groups sharing B reads); 256 thr/CTA.
// ============================================================================
#define NTOK 8192
#define KEIGHTH 1024
#define BANDLEN 1568                     // 1024 + 512 + readahead slack
#define ODD_OFF (3 * BANDLEN + 16)       // +16 floats: disjoint banks vs even
#define NCTA 128u

__device__ double g_acc[3];                                // sum_x2, sum_exp, sum_per_row
__device__ unsigned int g_done;
__device__ unsigned int g_bar;
__device__ __align__(16) uint32_t g_ph[8 * NTOK * 32];     // fp16 partials [ke][row][32 half2], 8MB
__device__ __align__(16) uint32_t g_w1p[512 * 4 * 32];     // [ks][jpos][lane] -> 4 uint32 each

__device__ __forceinline__ uint32_t pack_f16x2(float lo, float hi) {
    uint32_t r;
    asm("cvt.rn.f16x2.f32 %0, %1, %2;" : "=r"(r) : "f"(hi), "f"(lo));
    return r;
}
__device__ __forceinline__ uint64_t pack2f(float v) {
    uint64_t r;
    asm("mov.b64 %0, {%1, %1};" : "=l"(r) : "f"(v));
    return r;
}
// (x0,x1,x2 broadcast-packed) . (u,v,w packed f32 pairs) -> f16x2(lo,hi)
__device__ __forceinline__ uint32_t dot3cvt(uint64_t x0, uint64_t x1, uint64_t x2,
                                            uint64_t u, uint64_t v, uint64_t w) {
    uint32_t out;
    asm("{\n\t"
        ".reg .b64 t;\n\t"
        ".reg .b32 lo, hi;\n\t"
        "mul.rn.f32x2 t, %3, %6;\n\t"
        "fma.rn.f32x2 t, %2, %5, t;\n\t"
        "fma.rn.f32x2 t, %1, %4, t;\n\t"
        "mov.b64 {lo, hi}, t;\n\t"
        "cvt.rn.f16x2.f32 %0, hi, lo;\n\t"
        "}"
        : "=r"(out)
        : "l"(x0), "l"(x1), "l"(x2), "l"(u), "l"(v), "l"(w));
    return out;
}
__device__ __forceinline__ float elu1(float v) { return v > 0.f ? v : expm1f(v); }

// m16n8k16 fp16 in / fp16 acc: D = 2 regs (d0: rows g cols 2t,2t+1; d1: rows g+8)
#define MMA_F16(d0,d1,a0,a1,a2,a3,b0,b1) \
    asm volatile("mma.sync.aligned.m16n8k16.row.col.f16.f16.f16.f16 " \
                 "{%0,%1}, {%2,%3,%4,%5}, {%6,%7}, {%0,%1};" \
                 : "+r"(d0), "+r"(d1) \
                 : "r"(a0), "r"(a1), "r"(a2), "r"(a3), "r"(b0), "r"(b1))

// Software grid barrier: all 128 CTAs co-resident (1 CTA/SM).
__device__ __forceinline__ void grid_bar(unsigned target) {
    __syncthreads();
    if (threadIdx.x == 0) {
        __threadfence();
        atomicAdd(&g_bar, 1u);
        while (*((volatile unsigned*)&g_bar) < target) {}
        __threadfence();
    }
    __syncthreads();
}

// ---------------------------------------------------------------------------
// Fused kernel. grid = 128 x 256 threads (8 warps, 64 rows/warp).
//   SMEM: band[9424] | w2s[4096] | z1s[4096] | w3s[64] | wsum[8] | rsum[2]
// ---------------------------------------------------------------------------
__global__ __launch_bounds__(256, 1) void fused_kernel(
        const float* __restrict__ x,  const float* __restrict__ W1,
        const float* __restrict__ W2, const float* __restrict__ W3,
        const float* __restrict__ regu2, const float* __restrict__ regu,
        const float* __restrict__ rl_p, float* __restrict__ out) {
    extern __shared__ float smem[];
    float* band = smem;                          // 9424 floats
    float* w2s  = smem + 9424;                   // 4096 (scratch in phase 0b)
    float* z1s  = smem + 9424 + 4096;            // 4096 ([64 rows][64 f])
    float* w3s  = z1s + 4096;                    // 64
    float* wsum = w3s + 64;                      // 8
    float* rsum = wsum + 8;                      // 2

    const int tid = threadIdx.x, warp = tid >> 5, lane = tid & 31;
    const int g = lane >> 2, t = lane & 3;
    const int b = blockIdx.x;
    const int it = b >> 3, ke = b & 7;
    const int i0 = it * 512, jbase = ke * KEIGHTH;

    if (b == 0 && tid == 0) { g_acc[0] = 0.0; g_acc[1] = 0.0; g_acc[2] = 0.0; }

    // ---- Phase 0a: stage band (even + shifted odd copy; o=0 lands in pad) ----
    for (int o = tid; o < BANDLEN; o += 256) {
        const int s0 = (i0 + jbase + o) & (NTOK - 1);
        const float v0 = x[s0], v1 = x[NTOK + s0], v2 = x[2 * NTOK + s0];
        band[o]               = v0;
        band[BANDLEN + o]     = v1;
        band[2 * BANDLEN + o] = v2;
        band[ODD_OFF + o - 1]               = v0;
        band[ODD_OFF + BANDLEN + o - 1]     = v1;
        band[ODD_OFF + 2 * BANDLEN + o - 1] = v2;
    }

    // ---- Phase 0b: W1 -> fp16 fragments, coalesced layout [ks][jpos][lane] ----
    {
        const float4* src = (const float4*)(W1 + b * 4096);   // 64 k-rows x 64
        float4* w4 = (float4*)w2s;
        #pragma unroll
        for (int i = 0; i < 4; i++) w4[tid + i * 256] = src[tid + i * 256];
        __syncthreads();
        #pragma unroll
        for (int h = 0; h < 2; h++) {
            const int idx = tid + h * 256;                    // 0..511
            const int ksl = idx >> 7, inner = idx & 127;
            const int ln = inner >> 2, jpos = inner & 3;
            uint32_t o4[4];
            #pragma unroll
            for (int j = 0; j < 4; j++) {
                const int q = jpos * 4 + j;
                const int nt = q >> 1, r = q & 1;
                const int k = ksl * 16 + (ln & 3) * 2 + r * 8;
                const int n = nt * 8 + (ln >> 2);
                o4[j] = pack_f16x2(w2s[k * 64 + n], w2s[(k + 1) * 64 + n]);
            }
            ((uint4*)g_w1p)[(b * 4 + ksl) * 128 + jpos * 32 + ln] =
                make_uint4(o4[0], o4[1], o4[2], o4[3]);
        }
        __syncthreads();
    }

    // ---- Phase 0c: stage W2/W3; reg sums for this CTA's 64 tokens (warp 0) ----
    #pragma unroll
    for (int tv = tid; tv < 4096; tv += 256) w2s[tv] = W2[tv];
    if (tid < 64) w3s[tid] = W3[tid];
    if (warp == 0) {
        float x2t = 0.f, et = 0.f;
        const float rl = rl_p[0];
        const float inv = 1.f / (2.f * rl * rl);
        #pragma unroll
        for (int k = 0; k < 2; k++) {
            const int tok = b * 64 + k * 32 + lane;
            const float a = x[tok], bb = x[NTOK + tok], c = x[2 * NTOK + tok];
            const float x2 = fmaf(a, a, fmaf(bb, bb, c * c));
            x2t += x2;
            et  += expf(x2 * inv);
        }
        #pragma unroll
        for (int o = 16; o > 0; o >>= 1) {
            x2t += __shfl_down_sync(0xFFFFFFFFu, x2t, o);
            et  += __shfl_down_sync(0xFFFFFFFFu, et, o);
        }
        if (lane == 0) { rsum[0] = x2t; rsum[1] = et; }
    }

    // row scalars: 8 positions (r0+8m), 3 channels, broadcast-packed
    const int r0 = i0 + warp * 64 + g;
    uint64_t xs[8][3];
    #pragma unroll
    for (int m = 0; m < 8; m++) {
        xs[m][0] = pack2f(x[r0 + 8 * m]);
        xs[m][1] = pack2f(x[NTOK + r0 + 8 * m]);
        xs[m][2] = pack2f(x[2 * NTOK + r0 + 8 * m]);
    }

    // ---- grid barrier 1: all g_w1p fragments written ----
    grid_bar(NCTA);

    // ---- Phase 1: corr-build + fp16 MMA mainloop ----
    const int par = g & 1;
    const int ib = (warp * 64 + g + 2 * t - par) >> 1;   // uint64 index (G0)
    const uint64_t* sb = (const uint64_t*)(band + (par ? ODD_OFF : 0));
    const uint64_t* p0 = sb + ib;
    const uint64_t* p1 = sb + (BANDLEN >> 1) + ib;
    const uint64_t* p2 = sb + BANDLEN + ib;

    // coalesced B-frag pointer: [ks][jpos][lane]
    const uint4* bp = (const uint4*)g_w1p + (size_t)(ke * 64) * 128 + lane;

    uint32_t acc[2][2][8][2];                            // [grp][strip][nt][d]
    #pragma unroll
    for (int gr = 0; gr < 2; gr++)
        #pragma unroll
        for (int s = 0; s < 2; s++)
            #pragma unroll
            for (int nt = 0; nt < 8; nt++) { acc[gr][s][nt][0] = 0u; acc[gr][s][nt][1] = 0u; }

    // carried pair chains: G0 at +0, G1 at +32 floats (=+16 u64)
    uint64_t u0 = p0[0],  u1 = p0[4],  u2 = p0[8];
    uint64_t v0 = p1[0],  v1 = p1[4],  v2 = p1[8];
    uint64_t w0 = p2[0],  w1 = p2[4],  w2 = p2[8];
    uint64_t U0 = p0[16], U1 = p0[20], U2 = p0[24];
    uint64_t V0 = p1[16], V1 = p1[20], V2 = p1[24];
    uint64_t W0 = p2[16], W1f = p2[20], W2f = p2[24];

    #pragma unroll 2
    for (int ks = 0; ks < 64; ks++) {
        const int e = ks * 8;
        // fresh pairs: G0 at +24,+32 ; G1 at +56,+64 (rel. thread base)
        const uint64_t u3 = p0[e + 12], u4 = p0[e + 16];
        const uint64_t v3 = p1[e + 12], v4 = p1[e + 16];
        const uint64_t w3 = p2[e + 12], w4 = p2[e + 16];
        const uint64_t U3 = p0[e + 28], U4 = p0[e + 32];
        const uint64_t V3 = p1[e + 28], V4 = p1[e + 32];
        const uint64_t W3 = p2[e + 28], W4 = p2[e + 32];

        // G0 A-frags (rows r0, +8, +16, +24)
        const uint32_t a0 = dot3cvt(xs[0][0], xs[0][1], xs[0][2], u0, v0, w0);
        const uint32_t a2 = dot3cvt(xs[0][0], xs[0][1], xs[0][2], u1, v1, w1);
        const uint32_t a1 = dot3cvt(xs[1][0], xs[1][1], xs[1][2], u1, v1, w1);
        const uint32_t a3 = dot3cvt(xs[1][0], xs[1][1], xs[1][2], u2, v2, w2);
        const uint32_t c0 = dot3cvt(xs[2][0], xs[2][1], xs[2][2], u2, v2, w2);
        const uint32_t c2 = dot3cvt(xs[2][0], xs[2][1], xs[2][2], u3, v3, w3);
        const uint32_t c1 = dot3cvt(xs[3][0], xs[3][1], xs[3][2], u3, v3, w3);
        const uint32_t c3 = dot3cvt(xs[3][0], xs[3][1], xs[3][2], u4, v4, w4);
        // G1 A-frags (rows r0+32, +40, +48, +56)
        const uint32_t e0 = dot3cvt(xs[4][0], xs[4][1], xs[4][2], U0, V0, W0);
        const uint32_t e2 = dot3cvt(xs[4][0], xs[4][1], xs[4][2], U1, V1, W1f);
        const uint32_t e1 = dot3cvt(xs[5][0], xs[5][1], xs[5][2], U1, V1, W1f);
        const uint32_t e3 = dot3cvt(xs[5][0], xs[5][1], xs[5][2], U2, V2, W2f);
        const uint32_t f0 = dot3cvt(xs[6][0], xs[6][1], xs[6][2], U2, V2, W2f);
        const uint32_t f2 = dot3cvt(xs[6][0], xs[6][1], xs[6][2], U3, V3, W3);
        const uint32_t f1 = dot3cvt(xs[7][0], xs[7][1], xs[7][2], U3, V3, W3);
        const uint32_t f3 = dot3cvt(xs[7][0], xs[7][1], xs[7][2], U4, V4, W4);

        // coalesced B-frags (shared by both groups)
        const uint4 B0 = bp[0], B1 = bp[32], B2 = bp[64], B3 = bp[96];
        bp += 128;

        MMA_F16(acc[0][0][0][0], acc[0][0][0][1], a0, a1, a2, a3, B0.x, B0.y);
        MMA_F16(acc[0][0][1][0], acc[0][0][1][1], a0, a1, a2, a3, B0.z, B0.w);
        MMA_F16(acc[0][0][2][0], acc[0][0][2][1], a0, a1, a2, a3, B1.x, B1.y);
        MMA_F16(acc[0][0][3][0], acc[0][0][3][1], a0, a1, a2, a3, B1.z, B1.w);
        MMA_F16(acc[0][0][4][0], acc[0][0][4][1], a0, a1, a2, a3, B2.x, B2.y);
        MMA_F16(acc[0][0][5][0], acc[0][0][5][1], a0, a1, a2, a3, B2.z, B2.w);
        MMA_F16(acc[0][0][6][0], acc[0][0][6][1], a0, a1, a2, a3, B3.x, B3.y);
        MMA_F16(acc[0][0][7][0], acc[0][0][7][1], a0, a1, a2, a3, B3.z, B3.w);

        MMA_F16(acc[0][1][0][0], acc[0][1][0][1], c0, c1, c2, c3, B0.x, B0.y);
        MMA_F16(acc[0][1][1][0], acc[0][1][1][1], c0, c1, c2, c3, B0.z, B0.w);
        MMA_F16(acc[0][1][2][0], acc[0][1][2][1], c0, c1, c2, c3, B1.x, B1.y);
        MMA_F16(acc[0][1][3][0], acc[0][1][3][1], c0, c1, c2, c3, B1.z, B1.w);
        MMA_F16(acc[0][1][4][0], acc[0][1][4][1], c0, c1, c2, c3, B2.x, B2.y);
        MMA_F16(acc[0][1][5][0], acc[0][1][5][1], c0, c1, c2, c3, B2.z, B2.w);
        MMA_F16(acc[0][1][6][0], acc[0][1][6][1], c0, c1, c2, c3, B3.x, B3.y);
        MMA_F16(acc[0][1][7][0], acc[0][1][7][1], c0, c1, c2, c3, B3.z, B3.w);

        MMA_F16(acc[1][0][0][0], acc[1][0][0][1], e0, e1, e2, e3, B0.x, B0.y);
        MMA_F16(acc[1][0][1][0], acc[1][0][1][1], e0, e1, e2, e3, B0.z, B0.w);
        MMA_F16(acc[1][0][2][0], acc[1][0][2][1], e0, e1, e2, e3, B1.x, B1.y);
        MMA_F16(acc[1][0][3][0], acc[1][0][3][1], e0, e1, e2, e3, B1.z, B1.w);
        MMA_F16(acc[1][0][4][0], acc[1][0][4][1], e0, e1, e2, e3, B2.x, B2.y);
        MMA_F16(acc[1][0][5][0], acc[1][0][5][1], e0, e1, e2, e3, B2.z, B2.w);
        MMA_F16(acc[1][0][6][0], acc[1][0][6][1], e0, e1, e2, e3, B3.x, B3.y);
        MMA_F16(acc[1][0][7][0], acc[1][0][7][1], e0, e1, e2, e3, B3.z, B3.w);

        MMA_F16(acc[1][1][0][0], acc[1][1][0][1], f0, f1, f2, f3, B0.x, B0.y);
        MMA_F16(acc[1][1][1][0], acc[1][1][1][1], f0, f1, f2, f3, B0.z, B0.w);
        MMA_F16(acc[1][1][2][0], acc[1][1][2][1], f0, f1, f2, f3, B1.x, B1.y);
        MMA_F16(acc[1][1][3][0], acc[1][1][3][1], f0, f1, f2, f3, B1.z, B1.w);
        MMA_F16(acc[1][1][4][0], acc[1][1][4][1], f0, f1, f2, f3, B2.x, B2.y);
        MMA_F16(acc[1][1][5][0], acc[1][1][5][1], f0, f1, f2, f3, B2.z, B2.w);
        MMA_F16(acc[1][1][6][0], acc[1][1][6][1], f0, f1, f2, f3, B3.x, B3.y);
        MMA_F16(acc[1][1][7][0], acc[1][1][7][1], f0, f1, f2, f3, B3.z, B3.w);

        u0 = u2; u1 = u3; u2 = u4;
        v0 = v2; v1 = v3; v2 = v4;
        w0 = w2; w1 = w3; w2 = w4;
        U0 = U2; U1 = U3; U2 = U4;
        V0 = V2; V1 = V3; V2 = V4;
        W0 = W2f; W1f = W3; W2f = W4;
    }

    // epilogue: fp16 partials, [ke][row][32 half2]
    #pragma unroll
    for (int gr = 0; gr < 2; gr++)
        #pragma unroll
        for (int s = 0; s < 2; s++) {
            const int rowA = r0 + gr * 32 + 16 * s;
            #pragma unroll
            for (int nt = 0; nt < 8; nt++) {
                g_ph[((size_t)ke * NTOK + rowA)     * 32 + nt * 4 + t] = acc[gr][s][nt][0];
                g_ph[((size_t)ke * NTOK + rowA + 8) * 32 + nt * 4 + t] = acc[gr][s][nt][1];
            }
        }

    // ---- grid barrier 2: all partials written ----
    grid_bar(2 * NCTA);

    // ---- Phase 2: MLP for this CTA's 64 rows (8 warps x 8 rows) ----
    const int rbase = b * 64 + warp * 8;
    #pragma unroll
    for (int rr = 0; rr < 8; rr++) {
        float px = 0.f, py = 0.f;
        #pragma unroll
        for (int q = 0; q < 8; q++) {
            const uint32_t uu = g_ph[((size_t)q * NTOK + rbase + rr) * 32 + lane];
            const float2 p = __half22float2(*reinterpret_cast<const __half2*>(&uu));
            px += p.x; py += p.y;
        }
        z1s[(warp * 8 + rr) * 64 + 2 * lane]     = elu1(px);
        z1s[(warp * 8 + rr) * 64 + 2 * lane + 1] = elu1(py);
    }
    __syncwarp();

    float2 m[8];
    #pragma unroll
    for (int rr = 0; rr < 8; rr++) m[rr] = make_float2(0.f, 0.f);
    const float2* w2p = (const float2*)w2s + lane;
    const float* zw = z1s + warp * 8 * 64;
    #pragma unroll 4
    for (int f1 = 0; f1 < 64; f1++) {
        const float2 w = w2p[f1 * 32];
        #pragma unroll
        for (int rr = 0; rr < 8; rr++) {
            const float z = zw[rr * 64 + f1];
            m[rr].x = fmaf(z, w.x, m[rr].x);
            m[rr].y = fmaf(z, w.y, m[rr].y);
        }
    }

    const float w3a = w3s[2 * lane], w3b = w3s[2 * lane + 1];
    float tot = 0.f;
    #pragma unroll
    for (int rr = 0; rr < 8; rr++) {
        float s = fmaf(elu1(m[rr].x), w3a, elu1(m[rr].y) * w3b);
        #pragma unroll
        for (int o = 16; o > 0; o >>= 1) s += __shfl_down_sync(0xFFFFFFFFu, s, o);
        if (lane == 0) tot += elu1(s);
    }
    if (lane == 0) wsum[warp] = tot;
    __syncthreads();

    if (tid == 0) {
        float s = 0.f;
        #pragma unroll
        for (int wv = 0; wv < 8; wv++) s += wsum[wv];
        atomicAdd(&g_acc[2], (double)s);
        atomicAdd(&g_acc[0], (double)rsum[0]);
        atomicAdd(&g_acc[1], (double)rsum[1]);
        __threadfence();
        const unsigned int done = atomicAdd(&g_done, 1u);
        if (done == NCTA - 1u) {
            const double t0 = atomicAdd(&g_acc[0], 0.0);
            const double t1 = atomicAdd(&g_acc[1], 0.0);
            const double t2 = atomicAdd(&g_acc[2], 0.0);
            out[0] = (float)(t2 / (double)NTOK
                             - (double)regu2[0] * t0
                             - (double)regu[0] * t1);
            g_done = 0u;          // reset for next graph replay
            g_bar  = 0u;
        }
    }
}

// ---------------------------------------------------------------------------
// kernel_launch   d_in: 0=x 1=W1 2=W2 3=W3 4=regu2 5=regu 6=regu_length
// ---------------------------------------------------------------------------
extern "C" void kernel_launch(void* const* d_in, const int* in_sizes, int n_in,
                              void* d_out, int out_size) {
    const float* x  = (const float*)d_in[0];
    const float* W1 = (const float*)d_in[1];
    const float* W2 = (const float*)d_in[2];
    const float* W3 = (const float*)d_in[3];
    const float* r2 = (const float*)d_in[4];
    const float* r  = (const float*)d_in[5];
    const float* rl = (const float*)d_in[6];
    float* out = (float*)d_out;

    static const int smem_bytes = (9424 + 4096 + 4096 + 64 + 8 + 2) * sizeof(float); // 70760
    cudaFuncSetAttribute(fused_kernel, cudaFuncAttributeMaxDynamicSharedMemorySize, smem_bytes);

    fused_kernel<<<128, 256, smem_bytes>>>(x, W1, W2, W3, r2, r, rl, out);
}

// round 11
// speedup vs baseline: 1.4863x; 1.1405x over previous
#include <cuda_runtime.h>
#include <cuda_fp16.h>
#include <cstdint>

// ============================================================================
//   x : (3, 8192) fp32   W1 : (8192, 64)   W2 : (64, 64)   W3 : (64, 1)
//   out = mean(per_row MLP(corr)) - regu2*sum(x2) - regu*sum(exp(x2/(2 rl^2)))
//   corr[i,j] = sum_c x[c,(i+j)%N] * x[c,i]
//
//   R11: back to 32 rows/warp but 512 thr/CTA (16 warps/SM, 4/SMSP) —
//   occupancy over tiling now that B-frags are coalesced (R10) and l1tex
//   has headroom. fp16 A/B/acc, persistent single kernel.
// ============================================================================
#define NTOK 8192
#define KEIGHTH 1024
#define BANDLEN 1568                     // 1024 + 512 + readahead slack
#define ODD_OFF (3 * BANDLEN + 16)       // +16 floats: disjoint banks vs even
#define NCTA 128u

__device__ double g_acc[3];                                // sum_x2, sum_exp, sum_per_row
__device__ unsigned int g_done;
__device__ unsigned int g_bar;
__device__ __align__(16) uint32_t g_ph[8 * NTOK * 32];     // fp16 partials [ke][row][32 half2]
__device__ __align__(16) uint32_t g_w1p[512 * 4 * 32];     // [ks][jpos][lane] -> 4 uint32 each

__device__ __forceinline__ uint32_t pack_f16x2(float lo, float hi) {
    uint32_t r;
    asm("cvt.rn.f16x2.f32 %0, %1, %2;" : "=r"(r) : "f"(hi), "f"(lo));
    return r;
}
__device__ __forceinline__ uint64_t pack2f(float v) {
    uint64_t r;
    asm("mov.b64 %0, {%1, %1};" : "=l"(r) : "f"(v));
    return r;
}
__device__ __forceinline__ uint32_t dot3cvt(uint64_t x0, uint64_t x1, uint64_t x2,
                                            uint64_t u, uint64_t v, uint64_t w) {
    uint32_t out;
    asm("{\n\t"
        ".reg .b64 t;\n\t"
        ".reg .b32 lo, hi;\n\t"
        "mul.rn.f32x2 t, %3, %6;\n\t"
        "fma.rn.f32x2 t, %2, %5, t;\n\t"
        "fma.rn.f32x2 t, %1, %4, t;\n\t"
        "mov.b64 {lo, hi}, t;\n\t"
        "cvt.rn.f16x2.f32 %0, hi, lo;\n\t"
        "}"
        : "=r"(out)
        : "l"(x0), "l"(x1), "l"(x2), "l"(u), "l"(v), "l"(w));
    return out;
}
__device__ __forceinline__ float elu1(float v) { return v > 0.f ? v : expm1f(v); }

#define MMA_F16(d0,d1,a0,a1,a2,a3,b0,b1) \
    asm volatile("mma.sync.aligned.m16n8k16.row.col.f16.f16.f16.f16 " \
                 "{%0,%1}, {%2,%3,%4,%5}, {%6,%7}, {%0,%1};" \
                 : "+r"(d0), "+r"(d1) \
                 : "r"(a0), "r"(a1), "r"(a2), "r"(a3), "r"(b0), "r"(b1))

// Software grid barrier: all 128 CTAs co-resident (1 CTA/SM).
__device__ __forceinline__ void grid_bar(unsigned target) {
    __syncthreads();
    if (threadIdx.x == 0) {
        __threadfence();
        atomicAdd(&g_bar, 1u);
        while (*((volatile unsigned*)&g_bar) < target) {}
        __threadfence();
    }
    __syncthreads();
}

// ---------------------------------------------------------------------------
// Fused kernel. grid = 128 x 512 threads (16 warps, 32 rows/warp).
//   SMEM: band[9424] | w2s[4096] | z1s[4096] | w3s[64] | wsum[16] | rsum[2]
// ---------------------------------------------------------------------------
__global__ __launch_bounds__(512, 1) void fused_kernel(
        const float* __restrict__ x,  const float* __restrict__ W1,
        const float* __restrict__ W2, const float* __restrict__ W3,
        const float* __restrict__ regu2, const float* __restrict__ regu,
        const float* __restrict__ rl_p, float* __restrict__ out) {
    extern __shared__ float smem[];
    float* band = smem;                          // 9424 floats
    float* w2s  = smem + 9424;                   // 4096 (scratch in phase 0b)
    float* z1s  = smem + 9424 + 4096;            // 4096 ([64 rows][64 f])
    float* w3s  = z1s + 4096;                    // 64
    float* wsum = w3s + 64;                      // 16
    float* rsum = wsum + 16;                     // 2

    const int tid = threadIdx.x, warp = tid >> 5, lane = tid & 31;
    const int g = lane >> 2, t = lane & 3;
    const int b = blockIdx.x;
    const int it = b >> 3, ke = b & 7;
    const int i0 = it * 512, jbase = ke * KEIGHTH;

    if (b == 0 && tid == 0) { g_acc[0] = 0.0; g_acc[1] = 0.0; g_acc[2] = 0.0; }

    // ---- Phase 0a: stage band (even + shifted odd copy; o=0 lands in pad) ----
    for (int o = tid; o < BANDLEN; o += 512) {
        const int s0 = (i0 + jbase + o) & (NTOK - 1);
        const float v0 = x[s0], v1 = x[NTOK + s0], v2 = x[2 * NTOK + s0];
        band[o]               = v0;
        band[BANDLEN + o]     = v1;
        band[2 * BANDLEN + o] = v2;
        band[ODD_OFF + o - 1]               = v0;
        band[ODD_OFF + BANDLEN + o - 1]     = v1;
        band[ODD_OFF + 2 * BANDLEN + o - 1] = v2;
    }

    // ---- Phase 0b: W1 -> fp16 fragments, coalesced layout [ks][jpos][lane] ----
    {
        const float4* src = (const float4*)(W1 + b * 4096);   // 64 k-rows x 64
        float4* w4 = (float4*)w2s;
        w4[tid]       = src[tid];
        w4[tid + 512] = src[tid + 512];
        __syncthreads();
        const int ksl = tid >> 7, inner = tid & 127;
        const int ln = inner >> 2, jpos = inner & 3;
        uint32_t o4[4];
        #pragma unroll
        for (int j = 0; j < 4; j++) {
            const int q = jpos * 4 + j;
            const int nt = q >> 1, r = q & 1;
            const int k = ksl * 16 + (ln & 3) * 2 + r * 8;
            const int n = nt * 8 + (ln >> 2);
            o4[j] = pack_f16x2(w2s[k * 64 + n], w2s[(k + 1) * 64 + n]);
        }
        ((uint4*)g_w1p)[(b * 4 + ksl) * 128 + jpos * 32 + ln] =
            make_uint4(o4[0], o4[1], o4[2], o4[3]);
        __syncthreads();
    }

    // ---- Phase 0c: stage W2/W3; reg sums for this CTA's 64 tokens (warp 0) ----
    #pragma unroll
    for (int tv = tid; tv < 4096; tv += 512) w2s[tv] = W2[tv];
    if (tid < 64) w3s[tid] = W3[tid];
    if (warp == 0) {
        float x2t = 0.f, et = 0.f;
        const float rl = rl_p[0];
        const float inv = 1.f / (2.f * rl * rl);
        #pragma unroll
        for (int k = 0; k < 2; k++) {
            const int tok = b * 64 + k * 32 + lane;
            const float a = x[tok], bb = x[NTOK + tok], c = x[2 * NTOK + tok];
            const float x2 = fmaf(a, a, fmaf(bb, bb, c * c));
            x2t += x2;
            et  += expf(x2 * inv);
        }
        #pragma unroll
        for (int o = 16; o > 0; o >>= 1) {
            x2t += __shfl_down_sync(0xFFFFFFFFu, x2t, o);
            et  += __shfl_down_sync(0xFFFFFFFFu, et, o);
        }
        if (lane == 0) { rsum[0] = x2t; rsum[1] = et; }
    }

    // row scalars: 4 positions (r0+8m), 3 channels, broadcast-packed
    const int r0 = i0 + warp * 32 + g;
    uint64_t xs[4][3];
    #pragma unroll
    for (int m = 0; m < 4; m++) {
        xs[m][0] = pack2f(x[r0 + 8 * m]);
        xs[m][1] = pack2f(x[NTOK + r0 + 8 * m]);
        xs[m][2] = pack2f(x[2 * NTOK + r0 + 8 * m]);
    }

    // ---- grid barrier 1: all g_w1p fragments written ----
    grid_bar(NCTA);

    // ---- Phase 1: corr-build + fp16 MMA mainloop ----
    const int par = g & 1;
    const int ib = (warp * 32 + g + 2 * t - par) >> 1;   // uint64 index
    const uint64_t* sb = (const uint64_t*)(band + (par ? ODD_OFF : 0));
    const uint64_t* p0 = sb + ib;
    const uint64_t* p1 = sb + (BANDLEN >> 1) + ib;
    const uint64_t* p2 = sb + BANDLEN + ib;

    // coalesced B-frag pointer: [ks][jpos][lane]
    const uint4* bp = (const uint4*)g_w1p + (size_t)(ke * 64) * 128 + lane;

    uint32_t acc[2][8][2];                               // [strip][nt][d]
    #pragma unroll
    for (int s = 0; s < 2; s++)
        #pragma unroll
        for (int nt = 0; nt < 8; nt++) { acc[s][nt][0] = 0u; acc[s][nt][1] = 0u; }

    uint64_t u0 = p0[0], u1 = p0[4], u2 = p0[8];
    uint64_t v0 = p1[0], v1 = p1[4], v2 = p1[8];
    uint64_t w0 = p2[0], w1 = p2[4], w2 = p2[8];

    #pragma unroll 2
    for (int ks = 0; ks < 64; ks++) {
        const int e = ks * 8;
        const uint64_t u3 = p0[e + 12], u4 = p0[e + 16];
        const uint64_t v3 = p1[e + 12], v4 = p1[e + 16];
        const uint64_t w3 = p2[e + 12], w4 = p2[e + 16];

        const uint32_t a0 = dot3cvt(xs[0][0], xs[0][1], xs[0][2], u0, v0, w0);
        const uint32_t a2 = dot3cvt(xs[0][0], xs[0][1], xs[0][2], u1, v1, w1);
        const uint32_t a1 = dot3cvt(xs[1][0], xs[1][1], xs[1][2], u1, v1, w1);
        const uint32_t a3 = dot3cvt(xs[1][0], xs[1][1], xs[1][2], u2, v2, w2);
        const uint32_t c0 = dot3cvt(xs[2][0], xs[2][1], xs[2][2], u2, v2, w2);
        const uint32_t c2 = dot3cvt(xs[2][0], xs[2][1], xs[2][2], u3, v3, w3);
        const uint32_t c1 = dot3cvt(xs[3][0], xs[3][1], xs[3][2], u3, v3, w3);
        const uint32_t c3 = dot3cvt(xs[3][0], xs[3][1], xs[3][2], u4, v4, w4);

        const uint4 B0 = bp[0], B1 = bp[32], B2 = bp[64], B3 = bp[96];
        bp += 128;

        MMA_F16(acc[0][0][0], acc[0][0][1], a0, a1, a2, a3, B0.x, B0.y);
        MMA_F16(acc[0][1][0], acc[0][1][1], a0, a1, a2, a3, B0.z, B0.w);
        MMA_F16(acc[0][2][0], acc[0][2][1], a0, a1, a2, a3, B1.x, B1.y);
        MMA_F16(acc[0][3][0], acc[0][3][1], a0, a1, a2, a3, B1.z, B1.w);
        MMA_F16(acc[0][4][0], acc[0][4][1], a0, a1, a2, a3, B2.x, B2.y);
        MMA_F16(acc[0][5][0], acc[0][5][1], a0, a1, a2, a3, B2.z, B2.w);
        MMA_F16(acc[0][6][0], acc[0][6][1], a0, a1, a2, a3, B3.x, B3.y);
        MMA_F16(acc[0][7][0], acc[0][7][1], a0, a1, a2, a3, B3.z, B3.w);

        MMA_F16(acc[1][0][0], acc[1][0][1], c0, c1, c2, c3, B0.x, B0.y);
        MMA_F16(acc[1][1][0], acc[1][1][1], c0, c1, c2, c3, B0.z, B0.w);
        MMA_F16(acc[1][2][0], acc[1][2][1], c0, c1, c2, c3, B1.x, B1.y);
        MMA_F16(acc[1][3][0], acc[1][3][1], c0, c1, c2, c3, B1.z, B1.w);
        MMA_F16(acc[1][4][0], acc[1][4][1], c0, c1, c2, c3, B2.x, B2.y);
        MMA_F16(acc[1][5][0], acc[1][5][1], c0, c1, c2, c3, B2.z, B2.w);
        MMA_F16(acc[1][6][0], acc[1][6][1], c0, c1, c2, c3, B3.x, B3.y);
        MMA_F16(acc[1][7][0], acc[1][7][1], c0, c1, c2, c3, B3.z, B3.w);

        u0 = u2; u1 = u3; u2 = u4;
        v0 = v2; v1 = v3; v2 = v4;
        w0 = w2; w1 = w3; w2 = w4;
    }

    // epilogue: fp16 partials, [ke][row][32 half2]
    #pragma unroll
    for (int s = 0; s < 2; s++) {
        const int rowA = r0 + 16 * s;
        #pragma unroll
        for (int nt = 0; nt < 8; nt++) {
            g_ph[((size_t)ke * NTOK + rowA)     * 32 + nt * 4 + t] = acc[s][nt][0];
            g_ph[((size_t)ke * NTOK + rowA + 8) * 32 + nt * 4 + t] = acc[s][nt][1];
        }
    }

    // ---- grid barrier 2: all partials written ----
    grid_bar(2 * NCTA);

    // ---- Phase 2: MLP for this CTA's 64 rows (16 warps x 4 rows) ----
    const int rbase = b * 64 + warp * 4;
    #pragma unroll
    for (int rr = 0; rr < 4; rr++) {
        float px = 0.f, py = 0.f;
        #pragma unroll
        for (int q = 0; q < 8; q++) {
            const uint32_t uu = g_ph[((size_t)q * NTOK + rbase + rr) * 32 + lane];
            const float2 p = __half22float2(*reinterpret_cast<const __half2*>(&uu));
            px += p.x; py += p.y;
        }
        z1s[(warp * 4 + rr) * 64 + 2 * lane]     = elu1(px);
        z1s[(warp * 4 + rr) * 64 + 2 * lane + 1] = elu1(py);
    }
    __syncwarp();

    float2 m[4];
    #pragma unroll
    for (int rr = 0; rr < 4; rr++) m[rr] = make_float2(0.f, 0.f);
    const float2* w2p = (const float2*)w2s + lane;
    const float* zw = z1s + warp * 4 * 64;
    #pragma unroll 8
    for (int f1 = 0; f1 < 64; f1++) {
        const float2 w = w2p[f1 * 32];
        #pragma unroll
        for (int rr = 0; rr < 4; rr++) {
            const float z = zw[rr * 64 + f1];
            m[rr].x = fmaf(z, w.x, m[rr].x);
            m[rr].y = fmaf(z, w.y, m[rr].y);
        }
    }

    const float w3a = w3s[2 * lane], w3b = w3s[2 * lane + 1];
    float tot = 0.f;
    #pragma unroll
    for (int rr = 0; rr < 4; rr++) {
        float s = fmaf(elu1(m[rr].x), w3a, elu1(m[rr].y) * w3b);
        #pragma unroll
        for (int o = 16; o > 0; o >>= 1) s += __shfl_down_sync(0xFFFFFFFFu, s, o);
        if (lane == 0) tot += elu1(s);
    }
    if (lane == 0) wsum[warp] = tot;
    __syncthreads();

    if (tid == 0) {
        float s = 0.f;
        #pragma unroll
        for (int wv = 0; wv < 16; wv++) s += wsum[wv];
        atomicAdd(&g_acc[2], (double)s);
        atomicAdd(&g_acc[0], (double)rsum[0]);
        atomicAdd(&g_acc[1], (double)rsum[1]);
        __threadfence();
        const unsigned int done = atomicAdd(&g_done, 1u);
        if (done == NCTA - 1u) {
            const double t0 = atomicAdd(&g_acc[0], 0.0);
            const double t1 = atomicAdd(&g_acc[1], 0.0);
            const double t2 = atomicAdd(&g_acc[2], 0.0);
            out[0] = (float)(t2 / (double)NTOK
                             - (double)regu2[0] * t0
                             - (double)regu[0] * t1);
            g_done = 0u;          // reset for next graph replay
            g_bar  = 0u;
        }
    }
}

// ---------------------------------------------------------------------------
// kernel_launch   d_in: 0=x 1=W1 2=W2 3=W3 4=regu2 5=regu 6=regu_length
// ---------------------------------------------------------------------------
extern "C" void kernel_launch(void* const* d_in, const int* in_sizes, int n_in,
                              void* d_out, int out_size) {
    const float* x  = (const float*)d_in[0];
    const float* W1 = (const float*)d_in[1];
    const float* W2 = (const float*)d_in[2];
    const float* W3 = (const float*)d_in[3];
    const float* r2 = (const float*)d_in[4];
    const float* r  = (const float*)d_in[5];
    const float* rl = (const float*)d_in[6];
    float* out = (float*)d_out;

    static const int smem_bytes = (9424 + 4096 + 4096 + 64 + 16 + 2) * sizeof(float); // 70792
    cudaFuncSetAttribute(fused_kernel, cudaFuncAttributeMaxDynamicSharedMemorySize, smem_bytes);

    fused_kernel<<<128, 512, smem_bytes>>>(x, W1, W2, W3, r2, r, rl, out);
}

// round 12
// speedup vs baseline: 1.5483x; 1.0417x over previous
#include <cuda_runtime.h>
#include <cuda_fp16.h>
#include <cstdint>

// ============================================================================
//   x : (3, 8192) fp32   W1 : (8192, 64)   W2 : (64, 64)   W3 : (64, 1)
//   out = mean(per_row MLP(corr)) - regu2*sum(x2) - regu*sum(exp(x2/(2 rl^2)))
//   corr[i,j] = sum_c x[c,(i+j)%N] * x[c,i]
//
//   R12: band stored as fp16 half2 pairs; corr dot3 via HFMA2 (no CVT,
//   LDS.32, shorter chain, fewer regs). 512 thr/CTA persistent kernel.
// ============================================================================
#define NTOK 8192
#define KEIGHTH 1024
#define NPAIRS 784                       // BANDLEN/2 = (1024+512+slack)/2
#define ODD_BASE 2352                    // 3*784; ≡16 mod 32 -> disjoint banks
#define NCTA 128u

__device__ double g_acc[3];                                // sum_x2, sum_exp, sum_per_row
__device__ unsigned int g_done;
__device__ unsigned int g_bar;
__device__ __align__(16) uint32_t g_ph[8 * NTOK * 32];     // fp16 partials [ke][row][32 half2]
__device__ __align__(16) uint32_t g_w1p[512 * 4 * 32];     // [ks][jpos][lane] -> 4 uint32 each

__device__ __forceinline__ uint32_t pack_f16x2(float lo, float hi) {
    uint32_t r;
    asm("cvt.rn.f16x2.f32 %0, %1, %2;" : "=r"(r) : "f"(hi), "f"(lo));
    return r;
}
__device__ __forceinline__ uint32_t bcast_h2(float v) {
    const __half h = __float2half_rn(v);
    const __half2 h2 = __half2half2(h);
    return *reinterpret_cast<const uint32_t*>(&h2);
}
// fp16 dot3: (x0,x1,x2 broadcast half2) . (u,v,w half2 pairs) -> half2 bits
__device__ __forceinline__ uint32_t dot3h(uint32_t x0, uint32_t x1, uint32_t x2,
                                          uint32_t u, uint32_t v, uint32_t w) {
    const __half2 r = __hfma2(*(const __half2*)&x0, *(const __half2*)&u,
                      __hfma2(*(const __half2*)&x1, *(const __half2*)&v,
                      __hmul2(*(const __half2*)&x2, *(const __half2*)&w)));
    return *reinterpret_cast<const uint32_t*>(&r);
}
__device__ __forceinline__ float elu1(float v) { return v > 0.f ? v : expm1f(v); }

#define MMA_F16(d0,d1,a0,a1,a2,a3,b0,b1) \
    asm volatile("mma.sync.aligned.m16n8k16.row.col.f16.f16.f16.f16 " \
                 "{%0,%1}, {%2,%3,%4,%5}, {%6,%7}, {%0,%1};" \
                 : "+r"(d0), "+r"(d1) \
                 : "r"(a0), "r"(a1), "r"(a2), "r"(a3), "r"(b0), "r"(b1))

// Software grid barrier: all 128 CTAs co-resident (1 CTA/SM).
__device__ __forceinline__ void grid_bar(unsigned target) {
    __syncthreads();
    if (threadIdx.x == 0) {
        __threadfence();
        atomicAdd(&g_bar, 1u);
        while (*((volatile unsigned*)&g_bar) < target) {}
        __threadfence();
    }
    __syncthreads();
}

// ---------------------------------------------------------------------------
// Fused kernel. grid = 128 x 512 threads (16 warps, 32 rows/warp).
//   SMEM (words): bnd[4704] | w2s[4096] | z1s[4096] | w3s[64] | wsum[16] | rsum[2]
// ---------------------------------------------------------------------------
__global__ __launch_bounds__(512, 1) void fused_kernel(
        const float* __restrict__ x,  const float* __restrict__ W1,
        const float* __restrict__ W2, const float* __restrict__ W3,
        const float* __restrict__ regu2, const float* __restrict__ regu,
        const float* __restrict__ rl_p, float* __restrict__ out) {
    extern __shared__ float smem[];
    uint32_t* bnd = (uint32_t*)smem;             // 4704 words (even 3x784 | odd 3x784)
    float* w2s  = smem + 4704;                   // 4096 (scratch in phase 0b)
    float* z1s  = smem + 4704 + 4096;            // 4096 ([64 rows][64 f])
    float* w3s  = z1s + 4096;                    // 64
    float* wsum = w3s + 64;                      // 16
    float* rsum = wsum + 16;                     // 2

    const int tid = threadIdx.x, warp = tid >> 5, lane = tid & 31;
    const int g = lane >> 2, t = lane & 3;
    const int b = blockIdx.x;
    const int it = b >> 3, ke = b & 7;
    const int i0 = it * 512, jbase = ke * KEIGHTH;

    if (b == 0 && tid == 0) { g_acc[0] = 0.0; g_acc[1] = 0.0; g_acc[2] = 0.0; }

    // ---- Phase 0a: stage band as fp16 pairs (even + shifted-by-1 odd) ----
    for (int p = tid; p < NPAIRS; p += 512) {
        const int e0 = (i0 + jbase + 2 * p)     & (NTOK - 1);
        const int e1 = (i0 + jbase + 2 * p + 1) & (NTOK - 1);
        const int e2 = (i0 + jbase + 2 * p + 2) & (NTOK - 1);
        #pragma unroll
        for (int c = 0; c < 3; c++) {
            const float a = x[c * NTOK + e0];
            const float bb = x[c * NTOK + e1];
            const float cc = x[c * NTOK + e2];
            bnd[c * NPAIRS + p]            = pack_f16x2(a, bb);
            bnd[ODD_BASE + c * NPAIRS + p] = pack_f16x2(bb, cc);
        }
    }

    // ---- Phase 0b: W1 -> fp16 fragments, coalesced layout [ks][jpos][lane] ----
    {
        const float4* src = (const float4*)(W1 + b * 4096);   // 64 k-rows x 64
        float4* w4 = (float4*)w2s;
        w4[tid]       = src[tid];
        w4[tid + 512] = src[tid + 512];
        __syncthreads();
        const int ksl = tid >> 7, inner = tid & 127;
        const int ln = inner >> 2, jpos = inner & 3;
        uint32_t o4[4];
        #pragma unroll
        for (int j = 0; j < 4; j++) {
            const int q = jpos * 4 + j;
            const int nt = q >> 1, r = q & 1;
            const int k = ksl * 16 + (ln & 3) * 2 + r * 8;
            const int n = nt * 8 + (ln >> 2);
            o4[j] = pack_f16x2(w2s[k * 64 + n], w2s[(k + 1) * 64 + n]);
        }
        ((uint4*)g_w1p)[(b * 4 + ksl) * 128 + jpos * 32 + ln] =
            make_uint4(o4[0], o4[1], o4[2], o4[3]);
        __syncthreads();
    }

    // ---- Phase 0c: stage W2/W3; reg sums for this CTA's 64 tokens (warp 0) ----
    #pragma unroll
    for (int tv = tid; tv < 4096; tv += 512) w2s[tv] = W2[tv];
    if (tid < 64) w3s[tid] = W3[tid];
    if (warp == 0) {
        float x2t = 0.f, et = 0.f;
        const float rl = rl_p[0];
        const float inv = 1.f / (2.f * rl * rl);
        #pragma unroll
        for (int k = 0; k < 2; k++) {
            const int tok = b * 64 + k * 32 + lane;
            const float a = x[tok], bb = x[NTOK + tok], c = x[2 * NTOK + tok];
            const float x2 = fmaf(a, a, fmaf(bb, bb, c * c));
            x2t += x2;
            et  += expf(x2 * inv);
        }
        #pragma unroll
        for (int o = 16; o > 0; o >>= 1) {
            x2t += __shfl_down_sync(0xFFFFFFFFu, x2t, o);
            et  += __shfl_down_sync(0xFFFFFFFFu, et, o);
        }
        if (lane == 0) { rsum[0] = x2t; rsum[1] = et; }
    }

    // row scalars: 4 positions (r0+8m), 3 channels, broadcast half2
    const int r0 = i0 + warp * 32 + g;
    uint32_t xs[4][3];
    #pragma unroll
    for (int m = 0; m < 4; m++) {
        xs[m][0] = bcast_h2(x[r0 + 8 * m]);
        xs[m][1] = bcast_h2(x[NTOK + r0 + 8 * m]);
        xs[m][2] = bcast_h2(x[2 * NTOK + r0 + 8 * m]);
    }

    // ---- grid barrier 1: all g_w1p fragments written ----
    grid_bar(NCTA);

    // ---- Phase 1: fp16 corr-build + fp16 MMA mainloop ----
    const int par = g & 1;
    const int ibp = (warp * 32 + g + 2 * t - par) >> 1;  // pair index
    const uint32_t* sb = bnd + (par ? ODD_BASE : 0);
    const uint32_t* p0 = sb + ibp;
    const uint32_t* p1 = sb + NPAIRS + ibp;
    const uint32_t* p2 = sb + 2 * NPAIRS + ibp;

    // coalesced B-frag pointer: [ks][jpos][lane]
    const uint4* bp = (const uint4*)g_w1p + (size_t)(ke * 64) * 128 + lane;

    uint32_t acc[2][8][2];                               // [strip][nt][d]
    #pragma unroll
    for (int s = 0; s < 2; s++)
        #pragma unroll
        for (int nt = 0; nt < 8; nt++) { acc[s][nt][0] = 0u; acc[s][nt][1] = 0u; }

    uint32_t u0 = p0[0], u1 = p0[4], u2 = p0[8];
    uint32_t v0 = p1[0], v1 = p1[4], v2 = p1[8];
    uint32_t w0 = p2[0], w1 = p2[4], w2 = p2[8];

    #pragma unroll 4
    for (int ks = 0; ks < 64; ks++) {
        const int e = ks * 8;
        const uint32_t u3 = p0[e + 12], u4 = p0[e + 16];
        const uint32_t v3 = p1[e + 12], v4 = p1[e + 16];
        const uint32_t w3 = p2[e + 12], w4 = p2[e + 16];

        const uint32_t a0 = dot3h(xs[0][0], xs[0][1], xs[0][2], u0, v0, w0);
        const uint32_t a2 = dot3h(xs[0][0], xs[0][1], xs[0][2], u1, v1, w1);
        const uint32_t a1 = dot3h(xs[1][0], xs[1][1], xs[1][2], u1, v1, w1);
        const uint32_t a3 = dot3h(xs[1][0], xs[1][1], xs[1][2], u2, v2, w2);
        const uint32_t c0 = dot3h(xs[2][0], xs[2][1], xs[2][2], u2, v2, w2);
        const uint32_t c2 = dot3h(xs[2][0], xs[2][1], xs[2][2], u3, v3, w3);
        const uint32_t c1 = dot3h(xs[3][0], xs[3][1], xs[3][2], u3, v3, w3);
        const uint32_t c3 = dot3h(xs[3][0], xs[3][1], xs[3][2], u4, v4, w4);

        const uint4 B0 = bp[0], B1 = bp[32], B2 = bp[64], B3 = bp[96];
        bp += 128;

        MMA_F16(acc[0][0][0], acc[0][0][1], a0, a1, a2, a3, B0.x, B0.y);
        MMA_F16(acc[0][1][0], acc[0][1][1], a0, a1, a2, a3, B0.z, B0.w);
        MMA_F16(acc[0][2][0], acc[0][2][1], a0, a1, a2, a3, B1.x, B1.y);
        MMA_F16(acc[0][3][0], acc[0][3][1], a0, a1, a2, a3, B1.z, B1.w);
        MMA_F16(acc[0][4][0], acc[0][4][1], a0, a1, a2, a3, B2.x, B2.y);
        MMA_F16(acc[0][5][0], acc[0][5][1], a0, a1, a2, a3, B2.z, B2.w);
        MMA_F16(acc[0][6][0], acc[0][6][1], a0, a1, a2, a3, B3.x, B3.y);
        MMA_F16(acc[0][7][0], acc[0][7][1], a0, a1, a2, a3, B3.z, B3.w);

        MMA_F16(acc[1][0][0], acc[1][0][1], c0, c1, c2, c3, B0.x, B0.y);
        MMA_F16(acc[1][1][0], acc[1][1][1], c0, c1, c2, c3, B0.z, B0.w);
        MMA_F16(acc[1][2][0], acc[1][2][1], c0, c1, c2, c3, B1.x, B1.y);
        MMA_F16(acc[1][3][0], acc[1][3][1], c0, c1, c2, c3, B1.z, B1.w);
        MMA_F16(acc[1][4][0], acc[1][4][1], c0, c1, c2, c3, B2.x, B2.y);
        MMA_F16(acc[1][5][0], acc[1][5][1], c0, c1, c2, c3, B2.z, B2.w);
        MMA_F16(acc[1][6][0], acc[1][6][1], c0, c1, c2, c3, B3.x, B3.y);
        MMA_F16(acc[1][7][0], acc[1][7][1], c0, c1, c2, c3, B3.z, B3.w);

        u0 = u2; u1 = u3; u2 = u4;
        v0 = v2; v1 = v3; v2 = v4;
        w0 = w2; w1 = w3; w2 = w4;
    }

    // epilogue: fp16 partials, [ke][row][32 half2]
    #pragma unroll
    for (int s = 0; s < 2; s++) {
        const int rowA = r0 + 16 * s;
        #pragma unroll
        for (int nt = 0; nt < 8; nt++) {
            g_ph[((size_t)ke * NTOK + rowA)     * 32 + nt * 4 + t] = acc[s][nt][0];
            g_ph[((size_t)ke * NTOK + rowA + 8) * 32 + nt * 4 + t] = acc[s][nt][1];
        }
    }

    // ---- grid barrier 2: all partials written ----
    grid_bar(2 * NCTA);

    // ---- Phase 2: MLP for this CTA's 64 rows (16 warps x 4 rows) ----
    const int rbase = b * 64 + warp * 4;
    #pragma unroll
    for (int rr = 0; rr < 4; rr++) {
        float px = 0.f, py = 0.f;
        #pragma unroll
        for (int q = 0; q < 8; q++) {
            const uint32_t uu = g_ph[((size_t)q * NTOK + rbase + rr) * 32 + lane];
            const float2 p = __half22float2(*reinterpret_cast<const __half2*>(&uu));
            px += p.x; py += p.y;
        }
        z1s[(warp * 4 + rr) * 64 + 2 * lane]     = elu1(px);
        z1s[(warp * 4 + rr) * 64 + 2 * lane + 1] = elu1(py);
    }
    __syncwarp();

    float2 m[4];
    #pragma unroll
    for (int rr = 0; rr < 4; rr++) m[rr] = make_float2(0.f, 0.f);
    const float2* w2p = (const float2*)w2s + lane;
    const float* zw = z1s + warp * 4 * 64;
    #pragma unroll 8
    for (int f1 = 0; f1 < 64; f1++) {
        const float2 w = w2p[f1 * 32];
        #pragma unroll
        for (int rr = 0; rr < 4; rr++) {
            const float z = zw[rr * 64 + f1];
            m[rr].x = fmaf(z, w.x, m[rr].x);
            m[rr].y = fmaf(z, w.y, m[rr].y);
        }
    }

    const float w3a = w3s[2 * lane], w3b = w3s[2 * lane + 1];
    float tot = 0.f;
    #pragma unroll
    for (int rr = 0; rr < 4; rr++) {
        float s = fmaf(elu1(m[rr].x), w3a, elu1(m[rr].y) * w3b);
        #pragma unroll
        for (int o = 16; o > 0; o >>= 1) s += __shfl_down_sync(0xFFFFFFFFu, s, o);
        if (lane == 0) tot += elu1(s);
    }
    if (lane == 0) wsum[warp] = tot;
    __syncthreads();

    if (tid == 0) {
        float s = 0.f;
        #pragma unroll
        for (int wv = 0; wv < 16; wv++) s += wsum[wv];
        atomicAdd(&g_acc[2], (double)s);
        atomicAdd(&g_acc[0], (double)rsum[0]);
        atomicAdd(&g_acc[1], (double)rsum[1]);
        __threadfence();
        const unsigned int done = atomicAdd(&g_done, 1u);
        if (done == NCTA - 1u) {
            const double t0 = atomicAdd(&g_acc[0], 0.0);
            const double t1 = atomicAdd(&g_acc[1], 0.0);
            const double t2 = atomicAdd(&g_acc[2], 0.0);
            out[0] = (float)(t2 / (double)NTOK
                             - (double)regu2[0] * t0
                             - (double)regu[0] * t1);
            g_done = 0u;          // reset for next graph replay
            g_bar  = 0u;
        }
    }
}

// ---------------------------------------------------------------------------
// kernel_launch   d_in: 0=x 1=W1 2=W2 3=W3 4=regu2 5=regu 6=regu_length
// ---------------------------------------------------------------------------
extern "C" void kernel_launch(void* const* d_in, const int* in_sizes, int n_in,
                              void* d_out, int out_size) {
    const float* x  = (const float*)d_in[0];
    const float* W1 = (const float*)d_in[1];
    const float* W2 = (const float*)d_in[2];
    const float* W3 = (const float*)d_in[3];
    const float* r2 = (const float*)d_in[4];
    const float* r  = (const float*)d_in[5];
    const float* rl = (const float*)d_in[6];
    float* out = (float*)d_out;

    static const int smem_bytes = (4704 + 4096 + 4096 + 64 + 16 + 2) * sizeof(float); // 51912
    cudaFuncSetAttribute(fused_kernel, cudaFuncAttributeMaxDynamicSharedMemorySize, smem_bytes);

    fused_kernel<<<128, 512, smem_bytes>>>(x, W1, W2, W3, r2, r, rl, out);
}

// round 13
// speedup vs baseline: 1.5725x; 1.0156x over previous
#include <cuda_runtime.h>
#include <cuda_fp16.h>
#include <cstdint>

// ============================================================================
//   x : (3, 8192) fp32   W1 : (8192, 64)   W2 : (64, 64)   W3 : (64, 1)
//   out = mean(per_row MLP(corr)) - regu2*sum(x2) - regu*sum(exp(x2/(2 rl^2)))
//   corr[i,j] = sum_c x[c,(i+j)%N] * x[c,i]
//
//   R13: B-fragments staged through cp.async double-buffered SMEM chunks
//   (8 k-steps = 16KB per chunk) -> LDS.128 instead of per-iter L2 LDG.
// ============================================================================
#define NTOK 8192
#define KEIGHTH 1024
#define NPAIRS 784                       // fp16 pair count per channel
#define ODD_BASE 2352                    // 3*784; ≡16 mod 32 -> disjoint banks
#define NCTA 128u

// smem word offsets
#define OFF_BND   0
#define OFF_W2S   4704
#define OFF_Z1S   (4704 + 4096)
#define OFF_BBUF  (4704 + 4096 + 4096)   // 12896; 2 x 4096 words (16KB each)
#define OFF_W3S   (OFF_BBUF + 8192)      // 21088
#define OFF_WSUM  (OFF_W3S + 64)
#define OFF_RSUM  (OFF_WSUM + 16)
#define SMEM_WORDS (OFF_RSUM + 2)        // 21170 words = 84680 B

__device__ double g_acc[3];                                // sum_x2, sum_exp, sum_per_row
__device__ unsigned int g_done;
__device__ unsigned int g_bar;
__device__ __align__(16) uint32_t g_ph[8 * NTOK * 32];     // fp16 partials [ke][row][32 half2]
__device__ __align__(16) uint32_t g_w1p[512 * 4 * 32];     // [ks][jpos][lane] -> 4 uint32 each

__device__ __forceinline__ uint32_t smem_u32(const void* p) {
    uint32_t a;
    asm("{ .reg .u64 t; cvta.to.shared.u64 t, %1; cvt.u32.u64 %0, t; }" : "=r"(a) : "l"(p));
    return a;
}
__device__ __forceinline__ void cpasync16(uint32_t dst, const void* src) {
    asm volatile("cp.async.ca.shared.global [%0], [%1], 16;" :: "r"(dst), "l"(src));
}
#define CPASYNC_COMMIT() asm volatile("cp.async.commit_group;" ::: "memory")
#define CPASYNC_WAIT1()  asm volatile("cp.async.wait_group 1;" ::: "memory")

__device__ __forceinline__ uint32_t pack_f16x2(float lo, float hi) {
    uint32_t r;
    asm("cvt.rn.f16x2.f32 %0, %1, %2;" : "=r"(r) : "f"(hi), "f"(lo));
    return r;
}
__device__ __forceinline__ uint32_t bcast_h2(float v) {
    const __half h = __float2half_rn(v);
    const __half2 h2 = __half2half2(h);
    return *reinterpret_cast<const uint32_t*>(&h2);
}
__device__ __forceinline__ uint32_t dot3h(uint32_t x0, uint32_t x1, uint32_t x2,
                                          uint32_t u, uint32_t v, uint32_t w) {
    const __half2 r = __hfma2(*(const __half2*)&x0, *(const __half2*)&u,
                      __hfma2(*(const __half2*)&x1, *(const __half2*)&v,
                      __hmul2(*(const __half2*)&x2, *(const __half2*)&w)));
    return *reinterpret_cast<const uint32_t*>(&r);
}
__device__ __forceinline__ float elu1(float v) { return v > 0.f ? v : expm1f(v); }

#define MMA_F16(d0,d1,a0,a1,a2,a3,b0,b1) \
    asm volatile("mma.sync.aligned.m16n8k16.row.col.f16.f16.f16.f16 " \
                 "{%0,%1}, {%2,%3,%4,%5}, {%6,%7}, {%0,%1};" \
                 : "+r"(d0), "+r"(d1) \
                 : "r"(a0), "r"(a1), "r"(a2), "r"(a3), "r"(b0), "r"(b1))

// Software grid barrier: all 128 CTAs co-resident (1 CTA/SM).
__device__ __forceinline__ void grid_bar(unsigned target) {
    __syncthreads();
    if (threadIdx.x == 0) {
        __threadfence();
        atomicAdd(&g_bar, 1u);
        while (*((volatile unsigned*)&g_bar) < target) {}
        __threadfence();
    }
    __syncthreads();
}

// ---------------------------------------------------------------------------
// Fused kernel. grid = 128 x 512 threads (16 warps, 32 rows/warp).
// ---------------------------------------------------------------------------
__global__ __launch_bounds__(512, 1) void fused_kernel(
        const float* __restrict__ x,  const float* __restrict__ W1,
        const float* __restrict__ W2, const float* __restrict__ W3,
        const float* __restrict__ regu2, const float* __restrict__ regu,
        const float* __restrict__ rl_p, float* __restrict__ out) {
    extern __shared__ float smem[];
    uint32_t* bnd = (uint32_t*)smem + OFF_BND;
    float* w2s  = smem + OFF_W2S;
    float* z1s  = smem + OFF_Z1S;
    const uint4* bsm = (const uint4*)(smem + OFF_BBUF);   // B double buffer
    float* w3s  = smem + OFF_W3S;
    float* wsum = smem + OFF_WSUM;
    float* rsum = smem + OFF_RSUM;

    const int tid = threadIdx.x, warp = tid >> 5, lane = tid & 31;
    const int g = lane >> 2, t = lane & 3;
    const int b = blockIdx.x;
    const int it = b >> 3, ke = b & 7;
    const int i0 = it * 512, jbase = ke * KEIGHTH;

    if (b == 0 && tid == 0) { g_acc[0] = 0.0; g_acc[1] = 0.0; g_acc[2] = 0.0; }

    // ---- Phase 0a: stage band as fp16 pairs (even + shifted-by-1 odd) ----
    for (int p = tid; p < NPAIRS; p += 512) {
        const int e0 = (i0 + jbase + 2 * p)     & (NTOK - 1);
        const int e1 = (i0 + jbase + 2 * p + 1) & (NTOK - 1);
        const int e2 = (i0 + jbase + 2 * p + 2) & (NTOK - 1);
        #pragma unroll
        for (int c = 0; c < 3; c++) {
            const float a = x[c * NTOK + e0];
            const float bb = x[c * NTOK + e1];
            const float cc = x[c * NTOK + e2];
            bnd[c * NPAIRS + p]            = pack_f16x2(a, bb);
            bnd[ODD_BASE + c * NPAIRS + p] = pack_f16x2(bb, cc);
        }
    }

    // ---- Phase 0b: W1 -> fp16 fragments, coalesced layout [ks][jpos][lane] ----
    {
        const float4* src = (const float4*)(W1 + b * 4096);   // 64 k-rows x 64
        float4* w4 = (float4*)w2s;
        w4[tid]       = src[tid];
        w4[tid + 512] = src[tid + 512];
        __syncthreads();
        const int ksl = tid >> 7, inner = tid & 127;
        const int ln = inner >> 2, jpos = inner & 3;
        uint32_t o4[4];
        #pragma unroll
        for (int j = 0; j < 4; j++) {
            const int q = jpos * 4 + j;
            const int nt = q >> 1, r = q & 1;
            const int k = ksl * 16 + (ln & 3) * 2 + r * 8;
            const int n = nt * 8 + (ln >> 2);
            o4[j] = pack_f16x2(w2s[k * 64 + n], w2s[(k + 1) * 64 + n]);
        }
        ((uint4*)g_w1p)[(b * 4 + ksl) * 128 + jpos * 32 + ln] =
            make_uint4(o4[0], o4[1], o4[2], o4[3]);
        __syncthreads();
    }

    // ---- Phase 0c: stage W2/W3; reg sums for this CTA's 64 tokens (warp 0) ----
    #pragma unroll
    for (int tv = tid; tv < 4096; tv += 512) w2s[tv] = W2[tv];
    if (tid < 64) w3s[tid] = W3[tid];
    if (warp == 0) {
        float x2t = 0.f, et = 0.f;
        const float rl = rl_p[0];
        const float inv = 1.f / (2.f * rl * rl);
        #pragma unroll
        for (int k = 0; k < 2; k++) {
            const int tok = b * 64 + k * 32 + lane;
            const float a = x[tok], bb = x[NTOK + tok], c = x[2 * NTOK + tok];
            const float x2 = fmaf(a, a, fmaf(bb, bb, c * c));
            x2t += x2;
            et  += expf(x2 * inv);
        }
        #pragma unroll
        for (int o = 16; o > 0; o >>= 1) {
            x2t += __shfl_down_sync(0xFFFFFFFFu, x2t, o);
            et  += __shfl_down_sync(0xFFFFFFFFu, et, o);
        }
        if (lane == 0) { rsum[0] = x2t; rsum[1] = et; }
    }

    // row scalars: 4 positions (r0+8m), 3 channels, broadcast half2
    const int r0 = i0 + warp * 32 + g;
    uint32_t xs[4][3];
    #pragma unroll
    for (int m = 0; m < 4; m++) {
        xs[m][0] = bcast_h2(x[r0 + 8 * m]);
        xs[m][1] = bcast_h2(x[NTOK + r0 + 8 * m]);
        xs[m][2] = bcast_h2(x[2 * NTOK + r0 + 8 * m]);
    }

    // ---- grid barrier 1: all g_w1p fragments written ----
    grid_bar(NCTA);

    // ---- Phase 1: fp16 corr-build + fp16 MMA, cp.async-staged B ----
    const int par = g & 1;
    const int ibp = (warp * 32 + g + 2 * t - par) >> 1;  // pair index
    const uint32_t* sb = bnd + (par ? ODD_BASE : 0);
    const uint32_t* p0 = sb + ibp;
    const uint32_t* p1 = sb + NPAIRS + ibp;
    const uint32_t* p2 = sb + 2 * NPAIRS + ibp;

    // cp.async staging: chunk = 8 k-steps = 1024 uint4 = 16KB; thread stages 2x16B
    const char* bgbase = (const char*)(g_w1p) + (size_t)(ke * 64) * 2048;  // 2KB per ks
    const uint32_t bs_addr = smem_u32(smem + OFF_BBUF);
    // prologue: stage chunks 0 and 1
    #pragma unroll
    for (int c = 0; c < 2; c++) {
        const char* srcc = bgbase + (size_t)c * 16384;
        const uint32_t dstc = bs_addr + c * 16384;
        cpasync16(dstc + tid * 16, srcc + tid * 16);
        cpasync16(dstc + (tid + 512) * 16, srcc + (size_t)(tid + 512) * 16);
        CPASYNC_COMMIT();
    }

    uint32_t acc[2][8][2];
    #pragma unroll
    for (int s = 0; s < 2; s++)
        #pragma unroll
        for (int nt = 0; nt < 8; nt++) { acc[s][nt][0] = 0u; acc[s][nt][1] = 0u; }

    uint32_t u0 = p0[0], u1 = p0[4], u2 = p0[8];
    uint32_t v0 = p1[0], v1 = p1[4], v2 = p1[8];
    uint32_t w0 = p2[0], w1 = p2[4], w2 = p2[8];

    for (int c = 0; c < 8; c++) {
        CPASYNC_WAIT1();                 // chunk c resident (<=1 group pending)
        __syncthreads();                 // visible to all warps

        const uint4* bc = bsm + (c & 1) * 1024 + lane;
        #pragma unroll
        for (int kk = 0; kk < 8; kk++) {
            const int ks = c * 8 + kk;
            const int e = ks * 8;
            const uint32_t u3 = p0[e + 12], u4 = p0[e + 16];
            const uint32_t v3 = p1[e + 12], v4 = p1[e + 16];
            const uint32_t w3 = p2[e + 12], w4 = p2[e + 16];

            const uint32_t a0 = dot3h(xs[0][0], xs[0][1], xs[0][2], u0, v0, w0);
            const uint32_t a2 = dot3h(xs[0][0], xs[0][1], xs[0][2], u1, v1, w1);
            const uint32_t a1 = dot3h(xs[1][0], xs[1][1], xs[1][2], u1, v1, w1);
            const uint32_t a3 = dot3h(xs[1][0], xs[1][1], xs[1][2], u2, v2, w2);
            const uint32_t c0f = dot3h(xs[2][0], xs[2][1], xs[2][2], u2, v2, w2);
            const uint32_t c2f = dot3h(xs[2][0], xs[2][1], xs[2][2], u3, v3, w3);
            const uint32_t c1f = dot3h(xs[3][0], xs[3][1], xs[3][2], u3, v3, w3);
            const uint32_t c3f = dot3h(xs[3][0], xs[3][1], xs[3][2], u4, v4, w4);

            const uint4 B0 = bc[kk * 128];
            const uint4 B1 = bc[kk * 128 + 32];
            const uint4 B2 = bc[kk * 128 + 64];
            const uint4 B3 = bc[kk * 128 + 96];

            MMA_F16(acc[0][0][0], acc[0][0][1], a0, a1, a2, a3, B0.x, B0.y);
            MMA_F16(acc[0][1][0], acc[0][1][1], a0, a1, a2, a3, B0.z, B0.w);
            MMA_F16(acc[0][2][0], acc[0][2][1], a0, a1, a2, a3, B1.x, B1.y);
            MMA_F16(acc[0][3][0], acc[0][3][1], a0, a1, a2, a3, B1.z, B1.w);
            MMA_F16(acc[0][4][0], acc[0][4][1], a0, a1, a2, a3, B2.x, B2.y);
            MMA_F16(acc[0][5][0], acc[0][5][1], a0, a1, a2, a3, B2.z, B2.w);
            MMA_F16(acc[0][6][0], acc[0][6][1], a0, a1, a2, a3, B3.x, B3.y);
            MMA_F16(acc[0][7][0], acc[0][7][1], a0, a1, a2, a3, B3.z, B3.w);

            MMA_F16(acc[1][0][0], acc[1][0][1], c0f, c1f, c2f, c3f, B0.x, B0.y);
            MMA_F16(acc[1][1][0], acc[1][1][1], c0f, c1f, c2f, c3f, B0.z, B0.w);
            MMA_F16(acc[1][2][0], acc[1][2][1], c0f, c1f, c2f, c3f, B1.x, B1.y);
            MMA_F16(acc[1][3][0], acc[1][3][1], c0f, c1f, c2f, c3f, B1.z, B1.w);
            MMA_F16(acc[1][4][0], acc[1][4][1], c0f, c1f, c2f, c3f, B2.x, B2.y);
            MMA_F16(acc[1][5][0], acc[1][5][1], c0f, c1f, c2f, c3f, B2.z, B2.w);
            MMA_F16(acc[1][6][0], acc[1][6][1], c0f, c1f, c2f, c3f, B3.x, B3.y);
            MMA_F16(acc[1][7][0], acc[1][7][1], c0f, c1f, c2f, c3f, B3.z, B3.w);

            u0 = u2; u1 = u3; u2 = u4;
            v0 = v2; v1 = v3; v2 = v4;
            w0 = w2; w1 = w3; w2 = w4;
        }

        __syncthreads();                 // all warps done with buf (c&1)
        if (c + 2 < 8) {                 // stage chunk c+2 into buf (c&1)
            const char* srcc = bgbase + (size_t)(c + 2) * 16384;
            const uint32_t dstc = bs_addr + (c & 1) * 16384;
            cpasync16(dstc + tid * 16, srcc + tid * 16);
            cpasync16(dstc + (tid + 512) * 16, srcc + (size_t)(tid + 512) * 16);
        }
        CPASYNC_COMMIT();                // commit (possibly empty) group to keep count
    }

    // epilogue: fp16 partials, [ke][row][32 half2]
    #pragma unroll
    for (int s = 0; s < 2; s++) {
        const int rowA = r0 + 16 * s;
        #pragma unroll
        for (int nt = 0; nt < 8; nt++) {
            g_ph[((size_t)ke * NTOK + rowA)     * 32 + nt * 4 + t] = acc[s][nt][0];
            g_ph[((size_t)ke * NTOK + rowA + 8) * 32 + nt * 4 + t] = acc[s][nt][1];
        }
    }

    // ---- grid barrier 2: all partials written ----
    grid_bar(2 * NCTA);

    // ---- Phase 2: MLP for this CTA's 64 rows (16 warps x 4 rows) ----
    const int rbase = b * 64 + warp * 4;
    #pragma unroll
    for (int rr = 0; rr < 4; rr++) {
        float px = 0.f, py = 0.f;
        #pragma unroll
        for (int q = 0; q < 8; q++) {
            const uint32_t uu = g_ph[((size_t)q * NTOK + rbase + rr) * 32 + lane];
            const float2 p = __half22float2(*reinterpret_cast<const __half2*>(&uu));
            px += p.x; py += p.y;
        }
        z1s[(warp * 4 + rr) * 64 + 2 * lane]     = elu1(px);
        z1s[(warp * 4 + rr) * 64 + 2 * lane + 1] = elu1(py);
    }
    __syncwarp();

    float2 m[4];
    #pragma unroll
    for (int rr = 0; rr < 4; rr++) m[rr] = make_float2(0.f, 0.f);
    const float2* w2p = (const float2*)w2s + lane;
    const float* zw = z1s + warp * 4 * 64;
    #pragma unroll 8
    for (int f1 = 0; f1 < 64; f1++) {
        const float2 w = w2p[f1 * 32];
        #pragma unroll
        for (int rr = 0; rr < 4; rr++) {
            const float z = zw[rr * 64 + f1];
            m[rr].x = fmaf(z, w.x, m[rr].x);
            m[rr].y = fmaf(z, w.y, m[rr].y);
        }
    }

    const float w3a = w3s[2 * lane], w3b = w3s[2 * lane + 1];
    float tot = 0.f;
    #pragma unroll
    for (int rr = 0; rr < 4; rr++) {
        float s = fmaf(elu1(m[rr].x), w3a, elu1(m[rr].y) * w3b);
        #pragma unroll
        for (int o = 16; o > 0; o >>= 1) s += __shfl_down_sync(0xFFFFFFFFu, s, o);
        if (lane == 0) tot += elu1(s);
    }
    if (lane == 0) wsum[warp] = tot;
    __syncthreads();

    if (tid == 0) {
        float s = 0.f;
        #pragma unroll
        for (int wv = 0; wv < 16; wv++) s += wsum[wv];
        atomicAdd(&g_acc[2], (double)s);
        atomicAdd(&g_acc[0], (double)rsum[0]);
        atomicAdd(&g_acc[1], (double)rsum[1]);
        __threadfence();
        const unsigned int done = atomicAdd(&g_done, 1u);
        if (done == NCTA - 1u) {
            const double t0 = atomicAdd(&g_acc[0], 0.0);
            const double t1 = atomicAdd(&g_acc[1], 0.0);
            const double t2 = atomicAdd(&g_acc[2], 0.0);
            out[0] = (float)(t2 / (double)NTOK
                             - (double)regu2[0] * t0
                             - (double)regu[0] * t1);
            g_done = 0u;          // reset for next graph replay
            g_bar  = 0u;
        }
    }
}

// ---------------------------------------------------------------------------
// kernel_launch   d_in: 0=x 1=W1 2=W2 3=W3 4=regu2 5=regu 6=regu_length
// ---------------------------------------------------------------------------
extern "C" void kernel_launch(void* const* d_in, const int* in_sizes, int n_in,
                              void* d_out, int out_size) {
    const float* x  = (const float*)d_in[0];
    const float* W1 = (const float*)d_in[1];
    const float* W2 = (const float*)d_in[2];
    const float* W3 = (const float*)d_in[3];
    const float* r2 = (const float*)d_in[4];
    const float* r  = (const float*)d_in[5];
    const float* rl = (const float*)d_in[6];
    float* out = (float*)d_out;

    static const int smem_bytes = SMEM_WORDS * sizeof(float);   // 84680
    cudaFuncSetAttribute(fused_kernel, cudaFuncAttributeMaxDynamicSharedMemorySize, smem_bytes);

    fused_kernel<<<128, 512, smem_bytes>>>(x, W1, W2, W3, r2, r, rl, out);
}